// round 1
// baseline (speedup 1.0000x reference)
#include <cuda_runtime.h>
#include <cuda_bf16.h>
#include <cstdint>

// VQ layer: input (B=64, D=64, H=32, W=32) f32, codebook (K=1024, D=64) f32.
// N = B*H*W = 65536 points. For each point: argmin_k ||x - c_k||^2, then
// gather codebook row into embed laid out (B, D, H, W).
// Output buffer (float32): [idxes (65536 floats)] [embed (4194304 floats)]
// (adaptive to out_size in kernel_launch).

#define DDIM   64
#define KCODES 1024
#define HW     1024          // 32*32, channel stride in elements
#define NPTS   65536
#define CHUNK  128           // codes per smem tile (128*64*4 = 32 KB)

__device__ float g_cnorm[KCODES];

// ---------------------------------------------------------------------------
// packed fp32x2 fma (Blackwell): d = a*b + c elementwise on 2 packed floats
// ---------------------------------------------------------------------------
__device__ __forceinline__ unsigned long long ffma2(unsigned long long a,
                                                    unsigned long long b,
                                                    unsigned long long c) {
    unsigned long long d;
    asm("fma.rn.f32x2 %0, %1, %2, %3;" : "=l"(d) : "l"(a), "l"(b), "l"(c));
    return d;
}

__device__ __forceinline__ unsigned long long pack2(float lo, float hi) {
    unsigned long long r;
    asm("mov.b64 %0, {%1, %2};" : "=l"(r) : "f"(lo), "f"(hi));
    return r;
}

__device__ __forceinline__ float unpack_sum(unsigned long long v) {
    float lo, hi;
    asm("mov.b64 {%0, %1}, %2;" : "=f"(lo), "=f"(hi) : "l"(v));
    return lo + hi;
}

// ---------------------------------------------------------------------------
// Kernel 0: ||c_k||^2 for every codebook row
// ---------------------------------------------------------------------------
__global__ void vq_cnorm_kernel(const float* __restrict__ codebook) {
    int k = blockIdx.x * blockDim.x + threadIdx.x;
    if (k >= KCODES) return;
    const float* row = codebook + (size_t)k * DDIM;
    float s = 0.f;
#pragma unroll
    for (int d = 0; d < DDIM; d++) {
        float v = row[d];
        s = fmaf(v, v, s);
    }
    g_cnorm[k] = s;
}

// ---------------------------------------------------------------------------
// Kernel 1: per-point argmin + embed gather
//   blockDim = 128, one point per thread, 512 blocks
// ---------------------------------------------------------------------------
__global__ __launch_bounds__(128)
void vq_main_kernel(const float* __restrict__ input,
                    const float* __restrict__ codebook,
                    float* __restrict__ out_idx,     // may be null
                    float* __restrict__ out_embed) { // may be null
    __shared__ float sc[CHUNK * DDIM];   // 32 KB codebook tile
    __shared__ float scn[CHUNK];

    const int point = blockIdx.x * 128 + threadIdx.x;   // < 65536
    const int b  = point >> 10;          // point / 1024
    const int hw = point & 1023;         // point % 1024

    // Load this point's feature vector: input[b, d, hw], stride HW between d.
    // Coalesced across threads (consecutive hw).
    const float* xp = input + ((size_t)b * DDIM) * HW + hw;
    unsigned long long x2[DDIM / 2];
#pragma unroll
    for (int i = 0; i < DDIM / 2; i++) {
        float lo = xp[(size_t)(2 * i) * HW];
        float hi = xp[(size_t)(2 * i + 1) * HW];
        x2[i] = pack2(lo, hi);
    }

    float best = __int_as_float(0x7f7fffff);  // FLT_MAX
    int bestk = 0;

    for (int kc = 0; kc < KCODES; kc += CHUNK) {
        __syncthreads();  // previous tile fully consumed
        // cooperative tile load: CHUNK*DDIM/4 = 2048 float4, 16 per thread
        {
            const float4* src = reinterpret_cast<const float4*>(codebook + (size_t)kc * DDIM);
            float4* dst = reinterpret_cast<float4*>(sc);
#pragma unroll
            for (int i = 0; i < (CHUNK * DDIM / 4) / 128; i++) {
                int idx = threadIdx.x + i * 128;
                dst[idx] = src[idx];
            }
            if (threadIdx.x < CHUNK) scn[threadIdx.x] = g_cnorm[kc + threadIdx.x];
        }
        __syncthreads();

#pragma unroll 2
        for (int k = 0; k < CHUNK; k++) {
            const ulonglong2* c2 = reinterpret_cast<const ulonglong2*>(sc + (size_t)k * DDIM);
            unsigned long long a0 = 0ull, a1 = 0ull, a2 = 0ull, a3 = 0ull;
#pragma unroll
            for (int i = 0; i < 8; i++) {
                ulonglong2 cA = c2[2 * i];
                ulonglong2 cB = c2[2 * i + 1];
                a0 = ffma2(x2[4 * i + 0], cA.x, a0);
                a1 = ffma2(x2[4 * i + 1], cA.y, a1);
                a2 = ffma2(x2[4 * i + 2], cB.x, a2);
                a3 = ffma2(x2[4 * i + 3], cB.y, a3);
            }
            float dot = unpack_sum(a0) + unpack_sum(a1)
                      + unpack_sum(a2) + unpack_sum(a3);
            float d2 = fmaf(-2.f, dot, scn[k]);
            if (d2 < best) { best = d2; bestk = kc + k; }
        }
    }

    if (out_idx) out_idx[point] = (float)bestk;

    if (out_embed) {
        // embed[b, d, hw] = codebook[bestk, d]; coalesced across hw per d.
        const float* crow = codebook + (size_t)bestk * DDIM;
        float* op = out_embed + ((size_t)b * DDIM) * HW + hw;
#pragma unroll
        for (int d = 0; d < DDIM; d++) {
            op[(size_t)d * HW] = __ldg(crow + d);
        }
    }
}

// ---------------------------------------------------------------------------
extern "C" void kernel_launch(void* const* d_in, const int* in_sizes, int n_in,
                              void* d_out, int out_size) {
    const float* input    = (const float*)d_in[0];
    const float* codebook = (const float*)d_in[1];
    // Defensive: identify by size (input has 4194304 elems, codebook 65536)
    if (n_in >= 2 && in_sizes[0] == KCODES * DDIM && in_sizes[1] == NPTS * DDIM) {
        codebook = (const float*)d_in[0];
        input    = (const float*)d_in[1];
    }

    float* out = (float*)d_out;
    float* out_idx   = nullptr;
    float* out_embed = nullptr;
    if (out_size >= NPTS + NPTS * DDIM) {
        out_idx   = out;
        out_embed = out + NPTS;
    } else if (out_size == NPTS * DDIM) {
        out_embed = out;
    } else {
        out_idx = out;
    }

    vq_cnorm_kernel<<<KCODES / 128, 128>>>(codebook);
    vq_main_kernel<<<NPTS / 128, 128>>>(input, codebook, out_idx, out_embed);
}

// round 3
// speedup vs baseline: 1.6746x; 1.6746x over previous
#include <cuda_runtime.h>
#include <cstdint>

// VQ layer via legacy mma.sync tf32 (HMMA, base sm_100 target — tcgen05 is
// unavailable: harness builds compute_100 PTX without the 'a' feature set).
//
// input (B=64, D=64, H=32, W=32) f32 ; codebook (K=1024, D=64) f32
// out f32: [idxes (65536)] [embed (4194304, layout (B,D,H,W))]
//
// d2 = ||c||^2 - 2 x.c  (||x||^2 dropped; argmin-invariant)
// tf32 2-split: x = t1 + t2 (each exact tf32); dot via 3 passes
// t1x.t1c + t1x.t2c + t2x.t1c  (error ~2^-21, safer than fp32 reorder noise).

#define NPTS    65536
#define DDIM    64
#define KCODES  1024
#define HWD     1024
#define MBLK    128      // points per CTA
#define NCHUNK_CODES 128 // codes per chunk
#define NCHUNKS (KCODES / NCHUNK_CODES)   // 8

// Fragment-ordered operand storage.
// A block (128 pts): [ks 0..15][mtile 0..7][lane 0..31][a0,a1,a2,a3]
//   ks<8 = t1 cols, ks>=8 = t2 cols. 16*8*32*4 = 16384 floats / block.
// B chunk (128 codes): [ks 0..15][ntile 0..15][lane 0..31][b0,b1]
//   16*16*32*2 = 16384 floats / chunk.
__device__ float g_Xf[(NPTS / MBLK) * 16384];   // 512 blocks = 32 MB
__device__ float g_Cf[NCHUNKS * 16384];         // 8 chunks  = 512 KB
__device__ float g_cnorm[KCODES];

// ---- dynamic smem layout (bytes) ----
#define SO_SCN  0                       // 1024 f32 cnorm
#define SO_MK   4096                    // 128 i32 merge k
#define SO_MB   4608                    // 128 f32 merge best
#define SO_A    5120                    // 64 KB A frags
#define SO_B0   (SO_A + 65536)
#define SO_B1   (SO_B0 + 65536)
#define SMEM_TOTAL (SO_B1 + 65536)      // 201728 B

// ---------------------------------------------------------------------------
__device__ __forceinline__ uint32_t smem_u32(const void* p) {
    uint32_t a;
    asm("{ .reg .u64 t; cvta.to.shared.u64 t, %1; cvt.u32.u64 %0, t; }"
        : "=r"(a) : "l"(p));
    return a;
}
__device__ __forceinline__ float tf32_rna(float x) {
    uint32_t u;
    asm("cvt.rna.tf32.f32 %0, %1;" : "=r"(u) : "f"(x));
    return __uint_as_float(u);
}
__device__ __forceinline__ void cp_async16(uint32_t dst, const void* src) {
    asm volatile("cp.async.cg.shared.global [%0], [%1], 16;"
                 :: "r"(dst), "l"(src) : "memory");
}
#define CP_COMMIT() asm volatile("cp.async.commit_group;" ::: "memory")

__device__ __forceinline__ void lds128(uint32_t* r, uint32_t a) {
    asm volatile("ld.shared.v4.b32 {%0,%1,%2,%3}, [%4];"
                 : "=r"(r[0]), "=r"(r[1]), "=r"(r[2]), "=r"(r[3]) : "r"(a));
}
__device__ __forceinline__ void lds64(uint32_t* r, uint32_t a) {
    asm volatile("ld.shared.v2.b32 {%0,%1}, [%2];"
                 : "=r"(r[0]), "=r"(r[1]) : "r"(a));
}
__device__ __forceinline__ void mma_tf32(float* c, const uint32_t* a, const uint32_t* b) {
    asm volatile(
        "mma.sync.aligned.m16n8k8.row.col.f32.tf32.tf32.f32 "
        "{%0,%1,%2,%3}, {%4,%5,%6,%7}, {%8,%9}, {%0,%1,%2,%3};"
        : "+f"(c[0]), "+f"(c[1]), "+f"(c[2]), "+f"(c[3])
        : "r"(a[0]), "r"(a[1]), "r"(a[2]), "r"(a[3]), "r"(b[0]), "r"(b[1]));
}

// split value at concatenated column c (0-63: t1, 64-127: t2)
__device__ __forceinline__ float split_val(float x, int c) {
    float t1 = tf32_rna(x);
    return (c < 64) ? t1 : tf32_rna(x - t1);
}

// ---------------------------------------------------------------------------
// Prep: codebook -> g_Cf fragment order; cnorm
// ---------------------------------------------------------------------------
__global__ __launch_bounds__(256) void prep_codebook(const float* __restrict__ cb) {
    __shared__ float sc[128][65];
    const int t = threadIdx.x;
    const int kc = blockIdx.x * 128;   // chunk base code
    // load 128 codes x 64 dims (coalesced)
#pragma unroll
    for (int it = 0; it < 32; it++) {
        int idx = it * 256 + t;            // 8192 elems
        int n = idx >> 6, d = idx & 63;
        sc[n][d] = cb[(size_t)(kc + n) * DDIM + d];
    }
    __syncthreads();
    // cnorm
    if (t < 128) {
        float s = 0.f;
#pragma unroll
        for (int d = 0; d < DDIM; d++) s = fmaf(sc[t][d], sc[t][d], s);
        g_cnorm[kc + t] = s;
    }
    // fragment writes: 8192 float2
    float2* dst = reinterpret_cast<float2*>(g_Cf) + (size_t)blockIdx.x * 8192;
#pragma unroll
    for (int it = 0; it < 32; it++) {
        int fi = it * 256 + t;
        int ks = fi >> 9, nt = (fi >> 5) & 15, lane = fi & 31;
        int g = lane >> 2, tg = lane & 3;
        int n = nt * 8 + g;
        int c0 = ks * 8 + tg;              // 0..127 concat col
        int cc = (c0 < 64) ? c0 : c0 - 64;
        float b0 = split_val(sc[n][cc], c0);
        int c1 = c0 + 4;
        int cc1 = (c1 < 64) ? c1 : c1 - 64;
        float b1 = split_val(sc[n][cc1], c1);
        dst[fi] = make_float2(b0, b1);
    }
}

// ---------------------------------------------------------------------------
// Prep: input (B,D,HW) -> g_Xf fragment order (one 128-pt block per CTA)
// ---------------------------------------------------------------------------
__global__ __launch_bounds__(256) void prep_input(const float* __restrict__ in) {
    __shared__ float st[64][129];
    const int t = threadIdx.x;
    const int bm  = blockIdx.x;
    const int b   = bm >> 3;
    const int hw0 = (bm & 7) * 128;
    const float* src = in + (size_t)b * (DDIM * HWD) + hw0;
#pragma unroll
    for (int it = 0; it < 32; it++) {
        int idx = it * 256 + t;            // 8192
        int d = idx >> 7, i = idx & 127;
        st[d][i] = src[(size_t)d * HWD + i];
    }
    __syncthreads();
    float4* dst = reinterpret_cast<float4*>(g_Xf) + (size_t)bm * 4096;
#pragma unroll
    for (int it = 0; it < 16; it++) {
        int fi = it * 256 + t;             // 4096 float4
        int ks = fi >> 8, mt = (fi >> 5) & 7, lane = fi & 31;
        int g = lane >> 2, tg = lane & 3;
        int r0 = mt * 16 + g, r1 = r0 + 8;
        int c0 = ks * 8 + tg, c1 = c0 + 4;
        int cc0 = (c0 < 64) ? c0 : c0 - 64;
        int cc1 = (c1 < 64) ? c1 : c1 - 64;
        float a0 = split_val(st[cc0][r0], c0);
        float a1 = split_val(st[cc0][r1], c0);
        float a2 = split_val(st[cc1][r0], c1);
        float a3 = split_val(st[cc1][r1], c1);
        dst[fi] = make_float4(a0, a1, a2, a3);
    }
}

// ---------------------------------------------------------------------------
// Main kernel: 128 points x 1024 codes per CTA via HMMA tf32
// ---------------------------------------------------------------------------
__global__ __launch_bounds__(256, 1)
void vq_mma_kernel(const float* __restrict__ codebook,
                   float* __restrict__ out_idx,
                   float* __restrict__ out_embed) {
    extern __shared__ char smem[];
    const uint32_t sb = smem_u32(smem);
    const int tid  = threadIdx.x;
    const int wid  = tid >> 5;
    const int lane = tid & 31;
    const int g    = lane >> 2;
    const int tg   = lane & 3;
    const int wm   = wid & 3;     // M group: rows [wm*32, wm*32+32)
    const int wn   = wid >> 2;    // N half:  cols [wn*64, wn*64+64)

    // ---- prologue: cp.async A + cnorm + B chunk0 (group), then B chunk1 ----
    {
        const float4* Asrc = reinterpret_cast<const float4*>(g_Xf)
                             + (size_t)blockIdx.x * 4096;
#pragma unroll
        for (int it = 0; it < 16; it++) {
            int idx = it * 256 + tid;
            cp_async16(sb + SO_A + idx * 16, Asrc + idx);
        }
        const float4* cn4 = reinterpret_cast<const float4*>(g_cnorm);
        cp_async16(sb + SO_SCN + tid * 16, cn4 + tid);   // 256*16 = 4KB
        const float4* Bsrc = reinterpret_cast<const float4*>(g_Cf);
#pragma unroll
        for (int it = 0; it < 16; it++) {
            int idx = it * 256 + tid;
            cp_async16(sb + SO_B0 + idx * 16, Bsrc + idx);
        }
        CP_COMMIT();
#pragma unroll
        for (int it = 0; it < 16; it++) {
            int idx = it * 256 + tid;
            cp_async16(sb + SO_B1 + idx * 16, Bsrc + 4096 + idx);
        }
        CP_COMMIT();
    }

    const float* scn = reinterpret_cast<const float*>(smem + SO_SCN);
    float best[4];
    int   bestk[4];
#pragma unroll
    for (int i = 0; i < 4; i++) { best[i] = __int_as_float(0x7f7fffff); bestk[i] = 0; }

    // A frag base addr for this warp (2 mtiles: wm*2, wm*2+1)
    const uint32_t aBase = sb + SO_A + (uint32_t)(((wm * 2) * 32 + lane) * 16);
    const uint32_t bOffW = (uint32_t)(((wn * 8) * 32 + lane) * 8);

    for (int ch = 0; ch < NCHUNKS; ch++) {
        if (ch < NCHUNKS - 1) asm volatile("cp.async.wait_group 1;" ::: "memory");
        else                  asm volatile("cp.async.wait_group 0;" ::: "memory");
        __syncthreads();

        const uint32_t bBase = sb + ((ch & 1) ? SO_B1 : SO_B0) + bOffW;

        float acc[2][8][4];
#pragma unroll
        for (int mt = 0; mt < 2; mt++)
#pragma unroll
            for (int nt = 0; nt < 8; nt++)
#pragma unroll
                for (int j = 0; j < 4; j++) acc[mt][nt][j] = 0.f;

        // 3 passes: (A t1, B t1), (A t1, B t2), (A t2, B t1)
#pragma unroll
        for (int pass = 0; pass < 3; pass++) {
            const int aks0 = (pass == 2) ? 8 : 0;
            const int bks0 = (pass == 1) ? 8 : 0;
#pragma unroll
            for (int k8 = 0; k8 < 8; k8++) {
                uint32_t a[2][4];
#pragma unroll
                for (int mt = 0; mt < 2; mt++)
                    lds128(a[mt], aBase + (uint32_t)((((aks0 + k8) * 8 + mt) * 32) * 16));
                uint32_t bfr[8][2];
#pragma unroll
                for (int nt = 0; nt < 8; nt++)
                    lds64(bfr[nt], bBase + (uint32_t)((((bks0 + k8) * 16 + nt) * 32) * 8));
#pragma unroll
                for (int mt = 0; mt < 2; mt++)
#pragma unroll
                    for (int nt = 0; nt < 8; nt++)
                        mma_tf32(acc[mt][nt], a[mt], bfr[nt]);
            }
        }

        // ---- fold argmin for this chunk ----
        const int cb0 = ch * 128 + wn * 64;
#pragma unroll
        for (int mt = 0; mt < 2; mt++) {
#pragma unroll
            for (int nt = 0; nt < 8; nt++) {
                int col = cb0 + nt * 8 + tg * 2;
                float n0 = scn[col], n1 = scn[col + 1];
#pragma unroll
                for (int hi = 0; hi < 2; hi++) {
                    float d0 = fmaf(-2.f, acc[mt][nt][hi * 2 + 0], n0);
                    float d1 = fmaf(-2.f, acc[mt][nt][hi * 2 + 1], n1);
                    int bi = mt * 2 + hi;
                    if (d0 < best[bi]) { best[bi] = d0; bestk[bi] = col; }
                    if (d1 < best[bi]) { best[bi] = d1; bestk[bi] = col + 1; }
                }
            }
        }
        __syncthreads();   // everyone done with buf (ch&1) before re-filling it
        if (ch + 2 < NCHUNKS) {
            const float4* Bsrc = reinterpret_cast<const float4*>(g_Cf)
                                 + (size_t)(ch + 2) * 4096;
            const uint32_t bdst = sb + ((ch & 1) ? SO_B1 : SO_B0);
#pragma unroll
            for (int it = 0; it < 16; it++) {
                int idx = it * 256 + tid;
                cp_async16(bdst + idx * 16, Bsrc + idx);
            }
            CP_COMMIT();
        }
    }

    // ---- reduce over the 4 lanes (tg) sharing each row ----
#pragma unroll
    for (int i = 0; i < 4; i++) {
#pragma unroll
        for (int off = 1; off <= 2; off <<= 1) {
            float ob = __shfl_xor_sync(0xffffffffu, best[i], off);
            int   ok = __shfl_xor_sync(0xffffffffu, bestk[i], off);
            if (ob < best[i] || (ob == best[i] && ok < bestk[i])) {
                best[i] = ob; bestk[i] = ok;
            }
        }
    }

    // ---- merge the two warps (wn=0,1) sharing each row ----
    float* mb = reinterpret_cast<float*>(smem + SO_MB);
    int*   mk = reinterpret_cast<int*>(smem + SO_MK);
    if (wn == 0 && tg == 0) {
#pragma unroll
        for (int i = 0; i < 4; i++) {
            int r = wm * 32 + (i >> 1) * 16 + g + 8 * (i & 1);
            mb[r] = best[i]; mk[r] = bestk[i];
        }
    }
    __syncthreads();
    if (wn == 1 && tg == 0) {
#pragma unroll
        for (int i = 0; i < 4; i++) {
            int r = wm * 32 + (i >> 1) * 16 + g + 8 * (i & 1);
            float ob = mb[r]; int ok = mk[r];
            if (best[i] < ob || (best[i] == ob && bestk[i] < ok)) {
                mb[r] = best[i]; mk[r] = bestk[i];
            }
        }
    }
    __syncthreads();

    if (out_idx && tid < 128) out_idx[blockIdx.x * 128 + tid] = (float)mk[tid];

    // ---- embed gather: 256 threads, 32 channels each, coalesced over hw ----
    if (out_embed) {
        int p  = blockIdx.x * 128 + (tid & 127);
        int k  = mk[tid & 127];
        int b  = p >> 10, hw = p & 1023;
        int d0 = (tid >> 7) * 32;
        const float* crow = codebook + (size_t)k * DDIM + d0;
        float* op = out_embed + (size_t)b * (DDIM * HWD) + (size_t)d0 * HWD + hw;
#pragma unroll
        for (int d = 0; d < 32; d++) op[(size_t)d * HWD] = __ldg(crow + d);
    }
}

// ---------------------------------------------------------------------------
extern "C" void kernel_launch(void* const* d_in, const int* in_sizes, int n_in,
                              void* d_out, int out_size) {
    const float* input    = (const float*)d_in[0];
    const float* codebook = (const float*)d_in[1];
    if (n_in >= 2 && in_sizes[0] == KCODES * DDIM && in_sizes[1] == NPTS * DDIM) {
        codebook = (const float*)d_in[0];
        input    = (const float*)d_in[1];
    }

    float* out = (float*)d_out;
    float* out_idx   = nullptr;
    float* out_embed = nullptr;
    if (out_size >= NPTS + NPTS * DDIM) {
        out_idx   = out;
        out_embed = out + NPTS;
    } else if (out_size == NPTS * DDIM) {
        out_embed = out;
    } else {
        out_idx = out;
    }

    cudaFuncSetAttribute(vq_mma_kernel,
                         cudaFuncAttributeMaxDynamicSharedMemorySize, SMEM_TOTAL);

    prep_codebook<<<NCHUNKS, 256>>>(codebook);
    prep_input<<<NPTS / MBLK, 256>>>(input);
    vq_mma_kernel<<<NPTS / MBLK, 256, SMEM_TOTAL>>>(codebook, out_idx, out_embed);
}

// round 4
// speedup vs baseline: 1.8479x; 1.1035x over previous
#include <cuda_runtime.h>
#include <cstdint>

// VQ layer via legacy mma.sync tf32 (base sm_100 target; tcgen05 unavailable
// because the harness builds compute_100 PTX).
//
// input (B=64, D=64, H=32, W=32) f32 ; codebook (K=1024, D=64) f32
// out f32: [idxes (65536)] [embed (4194304, layout (B,D,H,W))]
//
// d2 = ||c||^2 - 2 x.c ; tf32 2-split dot (t1t1 + t1t2 + t2t1), error ~2^-21.
// R4: A-t1 fragments register-resident, software-pipelined fragment loads,
//     input prep fused into main kernel (staging in B1 buffer).

#define NPTS    65536
#define DDIM    64
#define KCODES  1024
#define HWD     1024
#define NCHUNKS 8        // 8 x 128 codes

// B fragments, chunk layout: [ks 0..15][nt 0..15][lane 0..31] float2
__device__ float g_Cf[NCHUNKS * 16384];
__device__ float g_cnorm[KCODES];

// ---- dynamic smem (bytes) ----
#define SO_SCN  0                       // 1024 f32 cnorm
#define SO_MK   4096                    // 128 i32
#define SO_MB   4608                    // 128 f32
#define SO_A    5120                    // 64 KB A fragments (t1|t2)
#define SO_B0   (SO_A + 65536)
#define SO_B1   (SO_B0 + 65536)         // doubles as 33.8 KB raw-input staging
#define SMEM_TOTAL (SO_B1 + 65536)      // 201728 B

#define STAGE_STRIDE 132                // floats per staged dim row (528 B, 16B mult)

// ---------------------------------------------------------------------------
__device__ __forceinline__ uint32_t smem_u32(const void* p) {
    uint32_t a;
    asm("{ .reg .u64 t; cvta.to.shared.u64 t, %1; cvt.u32.u64 %0, t; }"
        : "=r"(a) : "l"(p));
    return a;
}
__device__ __forceinline__ float tf32_rna(float x) {
    uint32_t u;
    asm("cvt.rna.tf32.f32 %0, %1;" : "=r"(u) : "f"(x));
    return __uint_as_float(u);
}
__device__ __forceinline__ void cp_async16(uint32_t dst, const void* src) {
    asm volatile("cp.async.cg.shared.global [%0], [%1], 16;"
                 :: "r"(dst), "l"(src) : "memory");
}
#define CP_COMMIT() asm volatile("cp.async.commit_group;" ::: "memory")

__device__ __forceinline__ void lds128(uint32_t* r, uint32_t a) {
    asm volatile("ld.shared.v4.b32 {%0,%1,%2,%3}, [%4];"
                 : "=r"(r[0]), "=r"(r[1]), "=r"(r[2]), "=r"(r[3]) : "r"(a));
}
__device__ __forceinline__ void lds64(uint32_t* r, uint32_t a) {
    asm volatile("ld.shared.v2.b32 {%0,%1}, [%2];"
                 : "=r"(r[0]), "=r"(r[1]) : "r"(a));
}
__device__ __forceinline__ void sts128(uint32_t a, float x, float y, float z, float w) {
    asm volatile("st.shared.v4.f32 [%0], {%1,%2,%3,%4};"
                 :: "r"(a), "f"(x), "f"(y), "f"(z), "f"(w) : "memory");
}
__device__ __forceinline__ void mma_tf32(float* c, const uint32_t* a, const uint32_t* b) {
    asm volatile(
        "mma.sync.aligned.m16n8k8.row.col.f32.tf32.tf32.f32 "
        "{%0,%1,%2,%3}, {%4,%5,%6,%7}, {%8,%9}, {%0,%1,%2,%3};"
        : "+f"(c[0]), "+f"(c[1]), "+f"(c[2]), "+f"(c[3])
        : "r"(a[0]), "r"(a[1]), "r"(a[2]), "r"(a[3]), "r"(b[0]), "r"(b[1]));
}
__device__ __forceinline__ float split_val(float x, int c) {
    float t1 = tf32_rna(x);
    return (c < 64) ? t1 : tf32_rna(x - t1);
}

// ---------------------------------------------------------------------------
// Prep: codebook -> g_Cf fragment order + cnorm. 32 blocks (chunk, quarter).
// ---------------------------------------------------------------------------
__global__ __launch_bounds__(256) void prep_codebook(const float* __restrict__ cb) {
    __shared__ float sc[32][65];
    const int t = threadIdx.x;
    const int c = blockIdx.x >> 2;     // chunk 0..7
    const int q = blockIdx.x & 3;      // quarter 0..3
    const int base = c * 128 + q * 32; // first code
    // load 32 codes x 64 dims
#pragma unroll
    for (int it = 0; it < 8; it++) {
        int idx = it * 256 + t;        // 2048
        int n = idx >> 6, d = idx & 63;
        sc[n][d] = cb[(size_t)(base + n) * DDIM + d];
    }
    __syncthreads();
    if (t < 32) {
        float s = 0.f;
#pragma unroll
        for (int d = 0; d < DDIM; d++) s = fmaf(sc[t][d], sc[t][d], s);
        g_cnorm[base + t] = s;
    }
    float2* dst = reinterpret_cast<float2*>(g_Cf);
#pragma unroll
    for (int it = 0; it < 8; it++) {
        int fi = it * 256 + t;                 // 2048 float2 per block
        int ks = fi >> 7, ntl = (fi >> 5) & 3, lane = fi & 31;
        int g = lane >> 2, tg = lane & 3;
        int nl = ntl * 8 + g;                  // local code 0..31
        int c0 = ks * 8 + tg, c1 = c0 + 4;
        int cc0 = (c0 < 64) ? c0 : c0 - 64;
        int cc1 = (c1 < 64) ? c1 : c1 - 64;
        float b0 = split_val(sc[nl][cc0], c0);
        float b1 = split_val(sc[nl][cc1], c1);
        dst[(size_t)c * 8192 + ks * 512 + (q * 4 + ntl) * 32 + lane] =
            make_float2(b0, b1);
    }
}

// ---------------------------------------------------------------------------
// Main: 128 points x 1024 codes per CTA (512 CTAs), HMMA tf32, fused A prep.
// ---------------------------------------------------------------------------
__global__ __launch_bounds__(256, 1)
void vq_mma_kernel(const float* __restrict__ input,
                   const float* __restrict__ codebook,
                   float* __restrict__ out_idx,
                   float* __restrict__ out_embed) {
    extern __shared__ char smem[];
    const uint32_t sb = smem_u32(smem);
    const int tid  = threadIdx.x;
    const int wid  = tid >> 5;
    const int lane = tid & 31;
    const int g    = lane >> 2;
    const int tg   = lane & 3;
    const int wm   = wid & 3;     // rows [wm*32, wm*32+32)
    const int wn   = wid >> 2;    // cols [wn*64, wn*64+64)

    const int bm  = blockIdx.x;
    const int b   = bm >> 3;
    const int hw0 = (bm & 7) * 128;

    // ---- G0: raw input tile (64 dims x 128 pts) -> staging (B1), + cnorm ----
    {
        const float* src = input + (size_t)b * (DDIM * HWD) + hw0;
#pragma unroll
        for (int it = 0; it < 8; it++) {
            int idx = it * 256 + tid;          // 2048 x 16B
            int row = idx >> 5, seg = idx & 31;
            cp_async16(sb + SO_B1 + (uint32_t)(row * (STAGE_STRIDE * 4) + seg * 16),
                       src + (size_t)row * HWD + seg * 4);
        }
        const float4* cn4 = reinterpret_cast<const float4*>(g_cnorm);
        cp_async16(sb + SO_SCN + tid * 16, cn4 + tid);
        CP_COMMIT();                            // G0
    }
    // ---- G1: B chunk 0 -> B0 ----
    {
        const float4* Bsrc = reinterpret_cast<const float4*>(g_Cf);
#pragma unroll
        for (int it = 0; it < 16; it++) {
            int idx = it * 256 + tid;
            cp_async16(sb + SO_B0 + idx * 16, Bsrc + idx);
        }
        CP_COMMIT();                            // G1
    }

    // ---- convert raw -> A fragments (t1|t2) ----
    asm volatile("cp.async.wait_group 1;" ::: "memory");   // G0 done
    __syncthreads();
    {
        const float* stage = reinterpret_cast<const float*>(smem + SO_B1);
#pragma unroll
        for (int it = 0; it < 16; it++) {
            int fi = it * 256 + tid;           // 4096 float4: [ks][mt][lane]
            int ks = fi >> 8, mt = (fi >> 5) & 7, ln = fi & 31;
            int gg = ln >> 2, t2 = ln & 3;
            int r0 = mt * 16 + gg, r1 = r0 + 8;
            int c0 = ks * 8 + t2, c1 = c0 + 4;
            int cc0 = (c0 < 64) ? c0 : c0 - 64;
            int cc1 = (c1 < 64) ? c1 : c1 - 64;
            float a0 = split_val(stage[cc0 * STAGE_STRIDE + r0], c0);
            float a1 = split_val(stage[cc0 * STAGE_STRIDE + r1], c0);
            float a2 = split_val(stage[cc1 * STAGE_STRIDE + r0], c1);
            float a3 = split_val(stage[cc1 * STAGE_STRIDE + r1], c1);
            sts128(sb + SO_A + fi * 16, a0, a1, a2, a3);
        }
    }
    __syncthreads();   // A ready; staging dead

    // ---- A-t1 fragments -> registers (used by passes 0 and 1) ----
    uint32_t At1[8][2][4];
#pragma unroll
    for (int ks = 0; ks < 8; ks++)
#pragma unroll
        for (int mt = 0; mt < 2; mt++)
            lds128(At1[ks][mt],
                   sb + SO_A + (uint32_t)(((ks * 8 + wm * 2 + mt) * 32 + lane) * 16));

    // ---- G2: B chunk 1 -> B1 ----
    {
        const float4* Bsrc = reinterpret_cast<const float4*>(g_Cf) + 4096;
#pragma unroll
        for (int it = 0; it < 16; it++) {
            int idx = it * 256 + tid;
            cp_async16(sb + SO_B1 + idx * 16, Bsrc + idx);
        }
        CP_COMMIT();                            // G2
    }

    const float* scn = reinterpret_cast<const float*>(smem + SO_SCN);
    float best[4];
    int   bestk[4];
#pragma unroll
    for (int i = 0; i < 4; i++) { best[i] = __int_as_float(0x7f7fffff); bestk[i] = 0; }

    const uint32_t bOffW = (uint32_t)((wn * 8 * 32 + lane) * 8);

    for (int ch = 0; ch < NCHUNKS; ch++) {
        if (ch < NCHUNKS - 1) asm volatile("cp.async.wait_group 1;" ::: "memory");
        else                  asm volatile("cp.async.wait_group 0;" ::: "memory");
        __syncthreads();

        const uint32_t bBase = sb + ((ch & 1) ? SO_B1 : SO_B0) + bOffW;

        float acc[2][8][4];
#pragma unroll
        for (int mt = 0; mt < 2; mt++)
#pragma unroll
            for (int nt = 0; nt < 8; nt++)
#pragma unroll
                for (int j = 0; j < 4; j++) acc[mt][nt][j] = 0.f;

        uint32_t bf[2][8][2];

        // ---- pass 0: A t1 (regs) x B t1 ; pass 1: A t1 x B t2 ----
#pragma unroll
        for (int pass = 0; pass < 2; pass++) {
            const int bks0 = pass ? 8 : 0;
#pragma unroll
            for (int nt = 0; nt < 8; nt++)
                lds64(bf[0][nt], bBase + (uint32_t)(((bks0 * 16 + nt) * 32) * 8));
#pragma unroll
            for (int k8 = 0; k8 < 8; k8++) {
                if (k8 < 7) {
#pragma unroll
                    for (int nt = 0; nt < 8; nt++)
                        lds64(bf[(k8 + 1) & 1][nt],
                              bBase + (uint32_t)((((bks0 + k8 + 1) * 16 + nt) * 32) * 8));
                }
#pragma unroll
                for (int mt = 0; mt < 2; mt++)
#pragma unroll
                    for (int nt = 0; nt < 8; nt++)
                        mma_tf32(acc[mt][nt], At1[k8][mt], bf[k8 & 1][nt]);
            }
        }

        // ---- pass 2: A t2 (smem, ks 8..15) x B t1 ----
        {
            uint32_t a2[2][2][4];
#pragma unroll
            for (int mt = 0; mt < 2; mt++)
                lds128(a2[0][mt],
                       sb + SO_A + (uint32_t)(((8 * 8 + wm * 2 + mt) * 32 + lane) * 16));
#pragma unroll
            for (int nt = 0; nt < 8; nt++)
                lds64(bf[0][nt], bBase + (uint32_t)(((nt) * 32) * 8));
#pragma unroll
            for (int k8 = 0; k8 < 8; k8++) {
                if (k8 < 7) {
#pragma unroll
                    for (int mt = 0; mt < 2; mt++)
                        lds128(a2[(k8 + 1) & 1][mt],
                               sb + SO_A +
                               (uint32_t)((((9 + k8) * 8 + wm * 2 + mt) * 32 + lane) * 16));
#pragma unroll
                    for (int nt = 0; nt < 8; nt++)
                        lds64(bf[(k8 + 1) & 1][nt],
                              bBase + (uint32_t)((((k8 + 1) * 16 + nt) * 32) * 8));
                }
#pragma unroll
                for (int mt = 0; mt < 2; mt++)
#pragma unroll
                    for (int nt = 0; nt < 8; nt++)
                        mma_tf32(acc[mt][nt], a2[k8 & 1][mt], bf[k8 & 1][nt]);
            }
        }

        // ---- argmin fold (cnorm hoisted per nt) ----
        {
            const int cb0 = ch * 128 + wn * 64;
            float cna[8], cnb[8];
#pragma unroll
            for (int nt = 0; nt < 8; nt++) {
                int col = cb0 + nt * 8 + tg * 2;
                cna[nt] = scn[col];
                cnb[nt] = scn[col + 1];
            }
#pragma unroll
            for (int mt = 0; mt < 2; mt++)
#pragma unroll
                for (int nt = 0; nt < 8; nt++) {
                    int col = cb0 + nt * 8 + tg * 2;
#pragma unroll
                    for (int hi = 0; hi < 2; hi++) {
                        float d0 = fmaf(-2.f, acc[mt][nt][hi * 2 + 0], cna[nt]);
                        float d1 = fmaf(-2.f, acc[mt][nt][hi * 2 + 1], cnb[nt]);
                        int bi = mt * 2 + hi;
                        if (d0 < best[bi]) { best[bi] = d0; bestk[bi] = col; }
                        if (d1 < best[bi]) { best[bi] = d1; bestk[bi] = col + 1; }
                    }
                }
        }

        __syncthreads();   // buffer (ch&1) fully consumed before refill
        if (ch + 2 < NCHUNKS) {
            const float4* Bsrc = reinterpret_cast<const float4*>(g_Cf)
                                 + (size_t)(ch + 2) * 4096;
            const uint32_t bdst = sb + ((ch & 1) ? SO_B1 : SO_B0);
#pragma unroll
            for (int it = 0; it < 16; it++) {
                int idx = it * 256 + tid;
                cp_async16(bdst + idx * 16, Bsrc + idx);
            }
            CP_COMMIT();
        }
    }

    // ---- reduce 4 lanes sharing each row ----
#pragma unroll
    for (int i = 0; i < 4; i++) {
#pragma unroll
        for (int off = 1; off <= 2; off <<= 1) {
            float ob = __shfl_xor_sync(0xffffffffu, best[i], off);
            int   ok = __shfl_xor_sync(0xffffffffu, bestk[i], off);
            if (ob < best[i] || (ob == best[i] && ok < bestk[i])) {
                best[i] = ob; bestk[i] = ok;
            }
        }
    }

    // ---- merge the two warps (wn) sharing each row ----
    float* mb = reinterpret_cast<float*>(smem + SO_MB);
    int*   mk = reinterpret_cast<int*>(smem + SO_MK);
    if (wn == 0 && tg == 0) {
#pragma unroll
        for (int i = 0; i < 4; i++) {
            int r = wm * 32 + (i >> 1) * 16 + g + 8 * (i & 1);
            mb[r] = best[i]; mk[r] = bestk[i];
        }
    }
    __syncthreads();
    if (wn == 1 && tg == 0) {
#pragma unroll
        for (int i = 0; i < 4; i++) {
            int r = wm * 32 + (i >> 1) * 16 + g + 8 * (i & 1);
            float ob = mb[r]; int ok = mk[r];
            if (best[i] < ob || (best[i] == ob && bestk[i] < ok)) {
                mb[r] = best[i]; mk[r] = bestk[i];
            }
        }
    }
    __syncthreads();

    if (out_idx && tid < 128) out_idx[bm * 128 + tid] = (float)mk[tid];

    // ---- embed gather ----
    if (out_embed) {
        int p  = bm * 128 + (tid & 127);
        int k  = mk[tid & 127];
        int bb = p >> 10, hw = p & 1023;
        int d0 = (tid >> 7) * 32;
        const float* crow = codebook + (size_t)k * DDIM + d0;
        float* op = out_embed + (size_t)bb * (DDIM * HWD) + (size_t)d0 * HWD + hw;
#pragma unroll
        for (int d = 0; d < 32; d++) op[(size_t)d * HWD] = __ldg(crow + d);
    }
}

// ---------------------------------------------------------------------------
extern "C" void kernel_launch(void* const* d_in, const int* in_sizes, int n_in,
                              void* d_out, int out_size) {
    const float* input    = (const float*)d_in[0];
    const float* codebook = (const float*)d_in[1];
    if (n_in >= 2 && in_sizes[0] == KCODES * DDIM && in_sizes[1] == NPTS * DDIM) {
        codebook = (const float*)d_in[0];
        input    = (const float*)d_in[1];
    }

    float* out = (float*)d_out;
    float* out_idx   = nullptr;
    float* out_embed = nullptr;
    if (out_size >= NPTS + NPTS * DDIM) {
        out_idx   = out;
        out_embed = out + NPTS;
    } else if (out_size == NPTS * DDIM) {
        out_embed = out;
    } else {
        out_idx = out;
    }

    cudaFuncSetAttribute(vq_mma_kernel,
                         cudaFuncAttributeMaxDynamicSharedMemorySize, SMEM_TOTAL);

    prep_codebook<<<32, 256>>>(codebook);
    vq_mma_kernel<<<NPTS / 128, 256, SMEM_TOTAL>>>(input, codebook, out_idx, out_embed);
}

// round 5
// speedup vs baseline: 1.9391x; 1.0494x over previous
#include <cuda_runtime.h>
#include <cstdint>

// VQ layer via legacy mma.sync tf32 (base sm_100 target; tcgen05 unavailable
// because the harness builds compute_100 PTX).
//
// input (B=64, D=64, H=32, W=32) f32 ; codebook (K=1024, D=64) f32
// out f32: [idxes (65536)] [embed (4194304, layout (B,D,H,W))]
//
// d2 = ||c||^2 - 2 x.c ; tf32 2-split dot (t1t1 + t1t2 + t2t1), error ~2^-21.
// R5: 16 warps (512 thr), warp tile 16x64, B-t1 fragments shared between the
//     At1 and At2 passes (one LDS feeds two MMA groups).

#define NPTS    65536
#define DDIM    64
#define KCODES  1024
#define HWD     1024
#define NCHUNKS 8        // 8 x 128 codes
#define NTHREADS 512

// B fragments, chunk layout: [ks 0..15][nt 0..15][lane 0..31] float2
__device__ float g_Cf[NCHUNKS * 16384];
__device__ float g_cnorm[KCODES];

// ---- dynamic smem (bytes) ----
#define SO_SCN  0                       // 1024 f32 cnorm
#define SO_MK   4096                    // 128 i32
#define SO_MB   4608                    // 128 f32
#define SO_A    5120                    // 64 KB A fragments (t1|t2)
#define SO_B0   (SO_A + 65536)
#define SO_B1   (SO_B0 + 65536)         // doubles as raw-input staging
#define SMEM_TOTAL (SO_B1 + 65536)      // 201728 B

#define STAGE_STRIDE 132                // floats per staged dim row (528 B)

// ---------------------------------------------------------------------------
__device__ __forceinline__ uint32_t smem_u32(const void* p) {
    uint32_t a;
    asm("{ .reg .u64 t; cvta.to.shared.u64 t, %1; cvt.u32.u64 %0, t; }"
        : "=r"(a) : "l"(p));
    return a;
}
__device__ __forceinline__ float tf32_rna(float x) {
    uint32_t u;
    asm("cvt.rna.tf32.f32 %0, %1;" : "=r"(u) : "f"(x));
    return __uint_as_float(u);
}
__device__ __forceinline__ void cp_async16(uint32_t dst, const void* src) {
    asm volatile("cp.async.cg.shared.global [%0], [%1], 16;"
                 :: "r"(dst), "l"(src) : "memory");
}
#define CP_COMMIT() asm volatile("cp.async.commit_group;" ::: "memory")

__device__ __forceinline__ void lds128(uint32_t* r, uint32_t a) {
    asm volatile("ld.shared.v4.b32 {%0,%1,%2,%3}, [%4];"
                 : "=r"(r[0]), "=r"(r[1]), "=r"(r[2]), "=r"(r[3]) : "r"(a));
}
__device__ __forceinline__ void lds64(uint32_t* r, uint32_t a) {
    asm volatile("ld.shared.v2.b32 {%0,%1}, [%2];"
                 : "=r"(r[0]), "=r"(r[1]) : "r"(a));
}
__device__ __forceinline__ void sts128(uint32_t a, float x, float y, float z, float w) {
    asm volatile("st.shared.v4.f32 [%0], {%1,%2,%3,%4};"
                 :: "r"(a), "f"(x), "f"(y), "f"(z), "f"(w) : "memory");
}
__device__ __forceinline__ void mma_tf32(float* c, const uint32_t* a, const uint32_t* b) {
    asm volatile(
        "mma.sync.aligned.m16n8k8.row.col.f32.tf32.tf32.f32 "
        "{%0,%1,%2,%3}, {%4,%5,%6,%7}, {%8,%9}, {%0,%1,%2,%3};"
        : "+f"(c[0]), "+f"(c[1]), "+f"(c[2]), "+f"(c[3])
        : "r"(a[0]), "r"(a[1]), "r"(a[2]), "r"(a[3]), "r"(b[0]), "r"(b[1]));
}
__device__ __forceinline__ float split_val(float x, int c) {
    float t1 = tf32_rna(x);
    return (c < 64) ? t1 : tf32_rna(x - t1);
}

// ---------------------------------------------------------------------------
// Prep: codebook -> g_Cf fragment order + cnorm. 32 blocks (chunk, quarter).
// ---------------------------------------------------------------------------
__global__ __launch_bounds__(256) void prep_codebook(const float* __restrict__ cb) {
    __shared__ float sc[32][65];
    const int t = threadIdx.x;
    const int c = blockIdx.x >> 2;
    const int q = blockIdx.x & 3;
    const int base = c * 128 + q * 32;
#pragma unroll
    for (int it = 0; it < 8; it++) {
        int idx = it * 256 + t;
        int n = idx >> 6, d = idx & 63;
        sc[n][d] = cb[(size_t)(base + n) * DDIM + d];
    }
    __syncthreads();
    if (t < 32) {
        float s = 0.f;
#pragma unroll
        for (int d = 0; d < DDIM; d++) s = fmaf(sc[t][d], sc[t][d], s);
        g_cnorm[base + t] = s;
    }
    float2* dst = reinterpret_cast<float2*>(g_Cf);
#pragma unroll
    for (int it = 0; it < 8; it++) {
        int fi = it * 256 + t;
        int ks = fi >> 7, ntl = (fi >> 5) & 3, lane = fi & 31;
        int g = lane >> 2, tg = lane & 3;
        int nl = ntl * 8 + g;
        int c0 = ks * 8 + tg, c1 = c0 + 4;
        int cc0 = (c0 < 64) ? c0 : c0 - 64;
        int cc1 = (c1 < 64) ? c1 : c1 - 64;
        float b0 = split_val(sc[nl][cc0], c0);
        float b1 = split_val(sc[nl][cc1], c1);
        dst[(size_t)c * 8192 + ks * 512 + (q * 4 + ntl) * 32 + lane] =
            make_float2(b0, b1);
    }
}

// ---------------------------------------------------------------------------
// Main: 128 points x 1024 codes per CTA (512 CTAs), 16 warps, HMMA tf32.
// ---------------------------------------------------------------------------
__global__ __launch_bounds__(NTHREADS, 1)
void vq_mma_kernel(const float* __restrict__ input,
                   const float* __restrict__ codebook,
                   float* __restrict__ out_idx,
                   float* __restrict__ out_embed) {
    extern __shared__ char smem[];
    const uint32_t sb = smem_u32(smem);
    const int tid  = threadIdx.x;
    const int wid  = tid >> 5;
    const int lane = tid & 31;
    const int g    = lane >> 2;
    const int tg   = lane & 3;
    const int wm   = wid & 7;     // mtile: rows [wm*16, wm*16+16)
    const int wn   = wid >> 3;    // cols [wn*64, wn*64+64)

    const int bm  = blockIdx.x;
    const int b   = bm >> 3;
    const int hw0 = (bm & 7) * 128;

    // ---- G0: raw input tile (64 dims x 128 pts) -> staging (B1), + cnorm ----
    {
        const float* src = input + (size_t)b * (DDIM * HWD) + hw0;
#pragma unroll
        for (int it = 0; it < 4; it++) {
            int idx = it * NTHREADS + tid;          // 2048 x 16B
            int row = idx >> 5, seg = idx & 31;
            cp_async16(sb + SO_B1 + (uint32_t)(row * (STAGE_STRIDE * 4) + seg * 16),
                       src + (size_t)row * HWD + seg * 4);
        }
        if (tid < 256) {
            const float4* cn4 = reinterpret_cast<const float4*>(g_cnorm);
            cp_async16(sb + SO_SCN + tid * 16, cn4 + tid);
        }
        CP_COMMIT();                            // G0
    }
    // ---- G1: B chunk 0 -> B0 ----
    {
        const float4* Bsrc = reinterpret_cast<const float4*>(g_Cf);
#pragma unroll
        for (int it = 0; it < 8; it++) {
            int idx = it * NTHREADS + tid;
            cp_async16(sb + SO_B0 + idx * 16, Bsrc + idx);
        }
        CP_COMMIT();                            // G1
    }

    // ---- convert raw -> A fragments (t1|t2) ----
    asm volatile("cp.async.wait_group 1;" ::: "memory");   // G0 done
    __syncthreads();
    {
        const float* stage = reinterpret_cast<const float*>(smem + SO_B1);
#pragma unroll
        for (int it = 0; it < 8; it++) {
            int fi = it * NTHREADS + tid;      // 4096 float4: [ks][mt][lane]
            int ks = fi >> 8, mt = (fi >> 5) & 7, ln = fi & 31;
            int gg = ln >> 2, t2 = ln & 3;
            int r0 = mt * 16 + gg, r1 = r0 + 8;
            int c0 = ks * 8 + t2, c1 = c0 + 4;
            int cc0 = (c0 < 64) ? c0 : c0 - 64;
            int cc1 = (c1 < 64) ? c1 : c1 - 64;
            float a0 = split_val(stage[cc0 * STAGE_STRIDE + r0], c0);
            float a1 = split_val(stage[cc0 * STAGE_STRIDE + r1], c0);
            float a2 = split_val(stage[cc1 * STAGE_STRIDE + r0], c1);
            float a3 = split_val(stage[cc1 * STAGE_STRIDE + r1], c1);
            sts128(sb + SO_A + fi * 16, a0, a1, a2, a3);
        }
    }
    __syncthreads();   // A ready; staging dead

    // ---- A-t1 fragments for this warp's mtile -> registers ----
    uint32_t At1[8][4];
#pragma unroll
    for (int ks = 0; ks < 8; ks++)
        lds128(At1[ks], sb + SO_A + (uint32_t)(((ks * 8 + wm) * 32 + lane) * 16));

    // ---- G2: B chunk 1 -> B1 ----
    {
        const float4* Bsrc = reinterpret_cast<const float4*>(g_Cf) + 4096;
#pragma unroll
        for (int it = 0; it < 8; it++) {
            int idx = it * NTHREADS + tid;
            cp_async16(sb + SO_B1 + idx * 16, Bsrc + idx);
        }
        CP_COMMIT();                            // G2
    }

    const float* scn = reinterpret_cast<const float*>(smem + SO_SCN);
    float best[2];
    int   bestk[2];
#pragma unroll
    for (int i = 0; i < 2; i++) { best[i] = __int_as_float(0x7f7fffff); bestk[i] = 0; }

    const uint32_t bOffW = (uint32_t)((wn * 8 * 32 + lane) * 8);
    const uint32_t aT2   = sb + SO_A + (uint32_t)(((8 * 8 + wm) * 32 + lane) * 16);

    for (int ch = 0; ch < NCHUNKS; ch++) {
        if (ch < NCHUNKS - 1) asm volatile("cp.async.wait_group 1;" ::: "memory");
        else                  asm volatile("cp.async.wait_group 0;" ::: "memory");
        __syncthreads();

        const uint32_t bBase = sb + ((ch & 1) ? SO_B1 : SO_B0) + bOffW;

        float acc[8][4];
#pragma unroll
        for (int nt = 0; nt < 8; nt++)
#pragma unroll
            for (int j = 0; j < 4; j++) acc[nt][j] = 0.f;

        uint32_t bf[2][8][2];
        uint32_t a2[2][4];

        // ---- merged passes on B-t1: (At1 x Bt1) + (At2 x Bt1) ----
        lds128(a2[0], aT2);
#pragma unroll
        for (int nt = 0; nt < 8; nt++)
            lds64(bf[0][nt], bBase + (uint32_t)((nt * 32) * 8));
#pragma unroll
        for (int k8 = 0; k8 < 8; k8++) {
            if (k8 < 7) {
                lds128(a2[(k8 + 1) & 1], aT2 + (uint32_t)(((k8 + 1) * 8 * 32) * 16));
#pragma unroll
                for (int nt = 0; nt < 8; nt++)
                    lds64(bf[(k8 + 1) & 1][nt],
                          bBase + (uint32_t)((((k8 + 1) * 16 + nt) * 32) * 8));
            }
#pragma unroll
            for (int nt = 0; nt < 8; nt++)
                mma_tf32(acc[nt], At1[k8], bf[k8 & 1][nt]);
#pragma unroll
            for (int nt = 0; nt < 8; nt++)
                mma_tf32(acc[nt], a2[k8 & 1], bf[k8 & 1][nt]);
        }

        // ---- pass on B-t2: (At1 x Bt2) ----
#pragma unroll
        for (int nt = 0; nt < 8; nt++)
            lds64(bf[0][nt], bBase + (uint32_t)(((8 * 16 + nt) * 32) * 8));
#pragma unroll
        for (int k8 = 0; k8 < 8; k8++) {
            if (k8 < 7) {
#pragma unroll
                for (int nt = 0; nt < 8; nt++)
                    lds64(bf[(k8 + 1) & 1][nt],
                          bBase + (uint32_t)((((8 + k8 + 1) * 16 + nt) * 32) * 8));
            }
#pragma unroll
            for (int nt = 0; nt < 8; nt++)
                mma_tf32(acc[nt], At1[k8], bf[k8 & 1][nt]);
        }

        // ---- argmin fold ----
        {
            const int cb0 = ch * 128 + wn * 64;
#pragma unroll
            for (int nt = 0; nt < 8; nt++) {
                int col = cb0 + nt * 8 + tg * 2;
                float n0 = scn[col], n1 = scn[col + 1];
#pragma unroll
                for (int hi = 0; hi < 2; hi++) {
                    float d0 = fmaf(-2.f, acc[nt][hi * 2 + 0], n0);
                    float d1 = fmaf(-2.f, acc[nt][hi * 2 + 1], n1);
                    if (d0 < best[hi]) { best[hi] = d0; bestk[hi] = col; }
                    if (d1 < best[hi]) { best[hi] = d1; bestk[hi] = col + 1; }
                }
            }
        }

        __syncthreads();   // buffer (ch&1) fully consumed before refill
        if (ch + 2 < NCHUNKS) {
            const float4* Bsrc = reinterpret_cast<const float4*>(g_Cf)
                                 + (size_t)(ch + 2) * 4096;
            const uint32_t bdst = sb + ((ch & 1) ? SO_B1 : SO_B0);
#pragma unroll
            for (int it = 0; it < 8; it++) {
                int idx = it * NTHREADS + tid;
                cp_async16(bdst + idx * 16, Bsrc + idx);
            }
            CP_COMMIT();
        }
    }

    // ---- reduce 4 lanes (tg) sharing each row ----
#pragma unroll
    for (int i = 0; i < 2; i++) {
#pragma unroll
        for (int off = 1; off <= 2; off <<= 1) {
            float ob = __shfl_xor_sync(0xffffffffu, best[i], off);
            int   ok = __shfl_xor_sync(0xffffffffu, bestk[i], off);
            if (ob < best[i] || (ob == best[i] && ok < bestk[i])) {
                best[i] = ob; bestk[i] = ok;
            }
        }
    }

    // ---- merge the two warps (wn) sharing each row ----
    float* mb = reinterpret_cast<float*>(smem + SO_MB);
    int*   mk = reinterpret_cast<int*>(smem + SO_MK);
    if (wn == 0 && tg == 0) {
#pragma unroll
        for (int i = 0; i < 2; i++) {
            int r = wm * 16 + g + 8 * i;
            mb[r] = best[i]; mk[r] = bestk[i];
        }
    }
    __syncthreads();
    if (wn == 1 && tg == 0) {
#pragma unroll
        for (int i = 0; i < 2; i++) {
            int r = wm * 16 + g + 8 * i;
            float ob = mb[r]; int ok = mk[r];
            if (best[i] < ob || (best[i] == ob && bestk[i] < ok)) {
                mb[r] = best[i]; mk[r] = bestk[i];
            }
        }
    }
    __syncthreads();

    if (out_idx && tid < 128) out_idx[bm * 128 + tid] = (float)mk[tid];

    // ---- embed gather: 512 threads, 16 channels each ----
    if (out_embed) {
        int p  = bm * 128 + (tid & 127);
        int k  = mk[tid & 127];
        int bb = p >> 10, hw = p & 1023;
        int d0 = (tid >> 7) * 16;
        const float* crow = codebook + (size_t)k * DDIM + d0;
        float* op = out_embed + (size_t)bb * (DDIM * HWD) + (size_t)d0 * HWD + hw;
#pragma unroll
        for (int d = 0; d < 16; d++) op[(size_t)d * HWD] = __ldg(crow + d);
    }
}

// ---------------------------------------------------------------------------
extern "C" void kernel_launch(void* const* d_in, const int* in_sizes, int n_in,
                              void* d_out, int out_size) {
    const float* input    = (const float*)d_in[0];
    const float* codebook = (const float*)d_in[1];
    if (n_in >= 2 && in_sizes[0] == KCODES * DDIM && in_sizes[1] == NPTS * DDIM) {
        codebook = (const float*)d_in[0];
        input    = (const float*)d_in[1];
    }

    float* out = (float*)d_out;
    float* out_idx   = nullptr;
    float* out_embed = nullptr;
    if (out_size >= NPTS + NPTS * DDIM) {
        out_idx   = out;
        out_embed = out + NPTS;
    } else if (out_size == NPTS * DDIM) {
        out_embed = out;
    } else {
        out_idx = out;
    }

    cudaFuncSetAttribute(vq_mma_kernel,
                         cudaFuncAttributeMaxDynamicSharedMemorySize, SMEM_TOTAL);

    prep_codebook<<<32, 256>>>(codebook);
    vq_mma_kernel<<<NPTS / 128, NTHREADS, SMEM_TOTAL>>>(input, codebook,
                                                        out_idx, out_embed);
}

// round 6
// speedup vs baseline: 3.0178x; 1.5563x over previous
#include <cuda_runtime.h>
#include <cuda_fp16.h>
#include <cstdint>

// VQ layer via legacy mma.sync fp16 m16n8k16 (base sm_100 target; tcgen05
// unavailable: harness builds compute_100 PTX).
//
// input (B=64, D=64, H=32, W=32) f32 ; codebook (K=1024, D=64) f32
// out f32: [idxes (65536)] [embed (4194304, layout (B,D,H,W))]
//
// d2 = ||c||^2 - 2 x.c ; fp16 2-split (h1 11-bit significand == tf32):
// dot = h1x.h1c + h1x.h2c + h2x.h1c, dropped term ~2^-22. f32 accumulate.
// R6: m16n8k16 halves MMA instruction count vs tf32 m16n8k8; A operand fully
// register-resident (32 regs); B fragments fp16 (half the LDS bytes).

#define NPTS    65536
#define DDIM    64
#define KCODES  1024
#define HWD     1024
#define NCHUNKS 8        // 8 x 128 codes
#define NTHREADS 512

// B fragments fp16, chunk layout: [ks 0..7][nt 0..15][lane 0..31] uint2
//   ks 0-3 = t1 cols (dims 0..63), ks 4-7 = t2 cols.
__device__ uint2 g_Cf[NCHUNKS * 8 * 16 * 32];   // 256 KB
__device__ float g_cnorm[KCODES];

// ---- dynamic smem (bytes) ----
#define SO_SCN   0                        // 1024 f32 cnorm
#define SO_MK    4096                     // 128 i32
#define SO_MB    4608                     // 128 f32
#define SO_A     5120                     // 32 KB A fp16 fragments
#define SO_B0    (SO_A + 32768)
#define SO_B1    (SO_B0 + 32768)
#define SO_STAGE (SO_B1 + 32768)          // 33792 B raw input staging
#define SMEM_TOTAL (SO_STAGE + 33792)     // 137216 B

#define STAGE_STRIDE 132                  // floats per staged dim row

// ---------------------------------------------------------------------------
__device__ __forceinline__ uint32_t smem_u32(const void* p) {
    uint32_t a;
    asm("{ .reg .u64 t; cvta.to.shared.u64 t, %1; cvt.u32.u64 %0, t; }"
        : "=r"(a) : "l"(p));
    return a;
}
__device__ __forceinline__ void cp_async16(uint32_t dst, const void* src) {
    asm volatile("cp.async.cg.shared.global [%0], [%1], 16;"
                 :: "r"(dst), "l"(src) : "memory");
}
#define CP_COMMIT() asm volatile("cp.async.commit_group;" ::: "memory")

__device__ __forceinline__ void lds128(uint32_t* r, uint32_t a) {
    asm volatile("ld.shared.v4.b32 {%0,%1,%2,%3}, [%4];"
                 : "=r"(r[0]), "=r"(r[1]), "=r"(r[2]), "=r"(r[3]) : "r"(a));
}
__device__ __forceinline__ void lds64(uint32_t* r, uint32_t a) {
    asm volatile("ld.shared.v2.b32 {%0,%1}, [%2];"
                 : "=r"(r[0]), "=r"(r[1]) : "r"(a));
}
__device__ __forceinline__ void sts128u(uint32_t a, uint32_t x, uint32_t y,
                                        uint32_t z, uint32_t w) {
    asm volatile("st.shared.v4.b32 [%0], {%1,%2,%3,%4};"
                 :: "r"(a), "r"(x), "r"(y), "r"(z), "r"(w) : "memory");
}
// mma.sync m16n8k16 f16 inputs, f32 accumulate
__device__ __forceinline__ void mma_f16(float* c, const uint32_t* a, const uint32_t* b) {
    asm volatile(
        "mma.sync.aligned.m16n8k16.row.col.f32.f16.f16.f32 "
        "{%0,%1,%2,%3}, {%4,%5,%6,%7}, {%8,%9}, {%0,%1,%2,%3};"
        : "+f"(c[0]), "+f"(c[1]), "+f"(c[2]), "+f"(c[3])
        : "r"(a[0]), "r"(a[1]), "r"(a[2]), "r"(a[3]), "r"(b[0]), "r"(b[1]));
}
__device__ __forceinline__ uint32_t packh2(__half lo, __half hi) {
    __half2 h = __halves2half2(lo, hi);
    return *reinterpret_cast<uint32_t*>(&h);
}
// value at concatenated column c (0-63: h1(dim c), 64-127: h2(dim c-64))
__device__ __forceinline__ __half split_h(float x, int c) {
    __half h1 = __float2half_rn(x);
    if (c < 64) return h1;
    return __float2half_rn(x - __half2float(h1));
}

// ---------------------------------------------------------------------------
// Prep: codebook -> g_Cf fp16 fragments + cnorm. 32 blocks (chunk, quarter).
// ---------------------------------------------------------------------------
__global__ __launch_bounds__(256) void prep_codebook(const float* __restrict__ cb) {
    __shared__ float sc[32][65];
    const int t = threadIdx.x;
    const int c = blockIdx.x >> 2;      // chunk 0..7
    const int q = blockIdx.x & 3;       // quarter 0..3
    const int base = c * 128 + q * 32;
#pragma unroll
    for (int it = 0; it < 8; it++) {
        int idx = it * 256 + t;
        int n = idx >> 6, d = idx & 63;
        sc[n][d] = cb[(size_t)(base + n) * DDIM + d];
    }
    __syncthreads();
    if (t < 32) {
        float s = 0.f;
#pragma unroll
        for (int d = 0; d < DDIM; d++) s = fmaf(sc[t][d], sc[t][d], s);
        g_cnorm[base + t] = s;
    }
    // 1024 fragment entries per block: [ks 0..7][ntl 0..3][lane]
#pragma unroll
    for (int it = 0; it < 4; it++) {
        int fi = it * 256 + t;
        int ks = fi >> 7, ntl = (fi >> 5) & 3, lane = fi & 31;
        int g = lane >> 2, tg = lane & 3;
        int nl = ntl * 8 + g;            // local code 0..31
        int c0 = ks * 16 + tg * 2;       // concat col of b0 low half
        int d0 = c0 & 63;                // (ks<4 -> c0<64; ks>=4 -> c0-64)
        uint32_t b0 = packh2(split_h(sc[nl][d0],     c0),
                             split_h(sc[nl][d0 + 1], c0 + 1));
        uint32_t b1 = packh2(split_h(sc[nl][d0 + 8], c0 + 8),
                             split_h(sc[nl][d0 + 9], c0 + 9));
        g_Cf[(((size_t)c * 8 + ks) * 16 + (q * 4 + ntl)) * 32 + lane] =
            make_uint2(b0, b1);
    }
}

// ---------------------------------------------------------------------------
// Main: 128 points x 1024 codes per CTA (512 CTAs), 16 warps, f16 HMMA.
// ---------------------------------------------------------------------------
__global__ __launch_bounds__(NTHREADS, 1)
void vq_mma_kernel(const float* __restrict__ input,
                   const float* __restrict__ codebook,
                   float* __restrict__ out_idx,
                   float* __restrict__ out_embed) {
    extern __shared__ char smem[];
    const uint32_t sb = smem_u32(smem);
    const int tid  = threadIdx.x;
    const int wid  = tid >> 5;
    const int lane = tid & 31;
    const int g    = lane >> 2;
    const int tg   = lane & 3;
    const int wm   = wid & 7;     // mtile: rows [wm*16, wm*16+16)
    const int wn   = wid >> 3;    // cols [wn*64, wn*64+64)

    const int bm  = blockIdx.x;
    const int b   = bm >> 3;
    const int hw0 = (bm & 7) * 128;

    // ---- G0: raw input tile (64 dims x 128 pts) -> staging, + cnorm ----
    {
        const float* src = input + (size_t)b * (DDIM * HWD) + hw0;
#pragma unroll
        for (int it = 0; it < 4; it++) {
            int idx = it * NTHREADS + tid;          // 2048 x 16B
            int row = idx >> 5, seg = idx & 31;
            cp_async16(sb + SO_STAGE + (uint32_t)(row * (STAGE_STRIDE * 4) + seg * 16),
                       src + (size_t)row * HWD + seg * 4);
        }
        if (tid < 256) {
            const float4* cn4 = reinterpret_cast<const float4*>(g_cnorm);
            cp_async16(sb + SO_SCN + tid * 16, cn4 + tid);
        }
        CP_COMMIT();                            // G0
    }
    // ---- G1: B chunk 0 -> B0 (32 KB) ----
    {
        const float4* Bsrc = reinterpret_cast<const float4*>(g_Cf);
#pragma unroll
        for (int it = 0; it < 4; it++) {
            int idx = it * NTHREADS + tid;
            cp_async16(sb + SO_B0 + idx * 16, Bsrc + idx);
        }
        CP_COMMIT();                            // G1
    }

    // ---- convert raw -> A fp16 fragments: 2048 entries [ks][mt][lane] ----
    asm volatile("cp.async.wait_group 1;" ::: "memory");   // G0 done
    __syncthreads();
    {
        const float* stage = reinterpret_cast<const float*>(smem + SO_STAGE);
#pragma unroll
        for (int it = 0; it < 4; it++) {
            int fi = it * NTHREADS + tid;
            int ks = fi >> 8, mt = (fi >> 5) & 7, ln = fi & 31;
            int gg = ln >> 2, t4 = ln & 3;
            int r0 = mt * 16 + gg, r1 = r0 + 8;
            int c0 = ks * 16 + t4 * 2;
            int d0 = c0 & 63;
            uint32_t a0 = packh2(split_h(stage[(d0)     * STAGE_STRIDE + r0], c0),
                                 split_h(stage[(d0 + 1) * STAGE_STRIDE + r0], c0 + 1));
            uint32_t a1 = packh2(split_h(stage[(d0)     * STAGE_STRIDE + r1], c0),
                                 split_h(stage[(d0 + 1) * STAGE_STRIDE + r1], c0 + 1));
            uint32_t a2 = packh2(split_h(stage[(d0 + 8) * STAGE_STRIDE + r0], c0 + 8),
                                 split_h(stage[(d0 + 9) * STAGE_STRIDE + r0], c0 + 9));
            uint32_t a3 = packh2(split_h(stage[(d0 + 8) * STAGE_STRIDE + r1], c0 + 8),
                                 split_h(stage[(d0 + 9) * STAGE_STRIDE + r1], c0 + 9));
            sts128u(sb + SO_A + fi * 16, a0, a1, a2, a3);
        }
    }
    __syncthreads();   // A ready

    // ---- ALL A fragments for this warp's mtile -> registers ----
    // At[0..3] = t1 ksteps, At[4..7] = t2 ksteps. 32 regs.
    uint32_t At[8][4];
#pragma unroll
    for (int ks = 0; ks < 8; ks++)
        lds128(At[ks], sb + SO_A + (uint32_t)(((ks * 8 + wm) * 32 + lane) * 16));

    // ---- G2: B chunk 1 -> B1 ----
    {
        const float4* Bsrc = reinterpret_cast<const float4*>(g_Cf) + 2048;
#pragma unroll
        for (int it = 0; it < 4; it++) {
            int idx = it * NTHREADS + tid;
            cp_async16(sb + SO_B1 + idx * 16, Bsrc + idx);
        }
        CP_COMMIT();                            // G2
    }

    const float* scn = reinterpret_cast<const float*>(smem + SO_SCN);
    float best[2];
    int   bestk[2];
#pragma unroll
    for (int i = 0; i < 2; i++) { best[i] = __int_as_float(0x7f7fffff); bestk[i] = 0; }

    const uint32_t bOffW = (uint32_t)((wn * 8 * 32 + lane) * 8);

    for (int ch = 0; ch < NCHUNKS; ch++) {
        if (ch < NCHUNKS - 1) asm volatile("cp.async.wait_group 1;" ::: "memory");
        else                  asm volatile("cp.async.wait_group 0;" ::: "memory");
        __syncthreads();

        const uint32_t bBase = sb + ((ch & 1) ? SO_B1 : SO_B0) + bOffW;

        float acc[8][4];
#pragma unroll
        for (int nt = 0; nt < 8; nt++)
#pragma unroll
            for (int j = 0; j < 4; j++) acc[nt][j] = 0.f;

        uint32_t bf[2][8][2];
        // load kstep 0
#pragma unroll
        for (int nt = 0; nt < 8; nt++)
            lds64(bf[0][nt], bBase + (uint32_t)(nt * 256));

        // ksteps 0-3: B-t1 (each feeds A-t1 and A-t2); ksteps 4-7: B-t2 x A-t1
#pragma unroll
        for (int k = 0; k < 8; k++) {
            if (k < 7) {
#pragma unroll
                for (int nt = 0; nt < 8; nt++)
                    lds64(bf[(k + 1) & 1][nt],
                          bBase + (uint32_t)(((k + 1) * 16 + nt) * 256));
            }
            if (k < 4) {
#pragma unroll
                for (int nt = 0; nt < 8; nt++)
                    mma_f16(acc[nt], At[k], bf[k & 1][nt]);
#pragma unroll
                for (int nt = 0; nt < 8; nt++)
                    mma_f16(acc[nt], At[k + 4], bf[k & 1][nt]);
            } else {
#pragma unroll
                for (int nt = 0; nt < 8; nt++)
                    mma_f16(acc[nt], At[k - 4], bf[k & 1][nt]);
            }
        }

        // ---- argmin fold ----
        {
            const int cb0 = ch * 128 + wn * 64;
#pragma unroll
            for (int nt = 0; nt < 8; nt++) {
                int col = cb0 + nt * 8 + tg * 2;
                float n0 = scn[col], n1 = scn[col + 1];
#pragma unroll
                for (int hi = 0; hi < 2; hi++) {
                    float d0 = fmaf(-2.f, acc[nt][hi * 2 + 0], n0);
                    float d1 = fmaf(-2.f, acc[nt][hi * 2 + 1], n1);
                    if (d0 < best[hi]) { best[hi] = d0; bestk[hi] = col; }
                    if (d1 < best[hi]) { best[hi] = d1; bestk[hi] = col + 1; }
                }
            }
        }

        __syncthreads();   // buffer (ch&1) fully consumed before refill
        if (ch + 2 < NCHUNKS) {
            const float4* Bsrc = reinterpret_cast<const float4*>(g_Cf)
                                 + (size_t)(ch + 2) * 2048;
            const uint32_t bdst = sb + ((ch & 1) ? SO_B1 : SO_B0);
#pragma unroll
            for (int it = 0; it < 4; it++) {
                int idx = it * NTHREADS + tid;
                cp_async16(bdst + idx * 16, Bsrc + idx);
            }
            CP_COMMIT();
        }
    }

    // ---- reduce 4 lanes (tg) sharing each row ----
#pragma unroll
    for (int i = 0; i < 2; i++) {
#pragma unroll
        for (int off = 1; off <= 2; off <<= 1) {
            float ob = __shfl_xor_sync(0xffffffffu, best[i], off);
            int   ok = __shfl_xor_sync(0xffffffffu, bestk[i], off);
            if (ob < best[i] || (ob == best[i] && ok < bestk[i])) {
                best[i] = ob; bestk[i] = ok;
            }
        }
    }

    // ---- merge the two warps (wn) sharing each row ----
    float* mb = reinterpret_cast<float*>(smem + SO_MB);
    int*   mk = reinterpret_cast<int*>(smem + SO_MK);
    if (wn == 0 && tg == 0) {
#pragma unroll
        for (int i = 0; i < 2; i++) {
            int r = wm * 16 + g + 8 * i;
            mb[r] = best[i]; mk[r] = bestk[i];
        }
    }
    __syncthreads();
    if (wn == 1 && tg == 0) {
#pragma unroll
        for (int i = 0; i < 2; i++) {
            int r = wm * 16 + g + 8 * i;
            float ob = mb[r]; int ok = mk[r];
            if (best[i] < ob || (best[i] == ob && bestk[i] < ok)) {
                mb[r] = best[i]; mk[r] = bestk[i];
            }
        }
    }
    __syncthreads();

    if (out_idx && tid < 128) out_idx[bm * 128 + tid] = (float)mk[tid];

    // ---- embed gather: 512 threads, 16 channels each ----
    if (out_embed) {
        int p  = bm * 128 + (tid & 127);
        int k  = mk[tid & 127];
        int bb = p >> 10, hw = p & 1023;
        int d0 = (tid >> 7) * 16;
        const float* crow = codebook + (size_t)k * DDIM + d0;
        float* op = out_embed + (size_t)bb * (DDIM * HWD) + (size_t)d0 * HWD + hw;
#pragma unroll
        for (int d = 0; d < 16; d++) op[(size_t)d * HWD] = __ldg(crow + d);
    }
}

// ---------------------------------------------------------------------------
extern "C" void kernel_launch(void* const* d_in, const int* in_sizes, int n_in,
                              void* d_out, int out_size) {
    const float* input    = (const float*)d_in[0];
    const float* codebook = (const float*)d_in[1];
    if (n_in >= 2 && in_sizes[0] == KCODES * DDIM && in_sizes[1] == NPTS * DDIM) {
        codebook = (const float*)d_in[0];
        input    = (const float*)d_in[1];
    }

    float* out = (float*)d_out;
    float* out_idx   = nullptr;
    float* out_embed = nullptr;
    if (out_size >= NPTS + NPTS * DDIM) {
        out_idx   = out;
        out_embed = out + NPTS;
    } else if (out_size == NPTS * DDIM) {
        out_embed = out;
    } else {
        out_idx = out;
    }

    cudaFuncSetAttribute(vq_mma_kernel,
                         cudaFuncAttributeMaxDynamicSharedMemorySize, SMEM_TOTAL);

    prep_codebook<<<32, 256>>>(codebook);
    vq_mma_kernel<<<NPTS / 128, NTHREADS, SMEM_TOTAL>>>(input, codebook,
                                                        out_idx, out_embed);
}

// round 7
// speedup vs baseline: 3.2032x; 1.0614x over previous
#include <cuda_runtime.h>
#include <cuda_fp16.h>
#include <cstdint>

// VQ layer via legacy mma.sync fp16 m16n8k16 (base sm_100 target).
//
// input (B=64, D=64, H=32, W=32) f32 ; codebook (K=1024, D=64) f32
// out f32: [idxes (65536)] [embed (4194304, layout (B,D,H,W))]
//
// d2 = ||c||^2 - 2 x.c ; fp16 2-split (h1 has tf32-grade 11-bit significand):
// dot = h1x.h1c + h1x.h2c + h2x.h1c, f32 accumulate, error ~2^-22.
// R7: warp tile 32x64 (each B fragment feeds 2 mtiles), 256-thread CTAs with
// 101 KB smem -> 2 CTAs/SM (independent barrier domains).

#define NPTS    65536
#define DDIM    64
#define KCODES  1024
#define HWD     1024
#define NCHUNKS 8        // 8 x 128 codes
#define NTHREADS 256

// B fragments fp16, chunk layout: [ks 0..7][nt 0..15][lane 0..31] uint2
//   ks 0-3 = h1 cols (dims 0..63), ks 4-7 = h2 cols.
__device__ uint2 g_Cf[NCHUNKS * 8 * 16 * 32];   // 256 KB (L2-resident)
__device__ float g_cnorm[KCODES];

// ---- dynamic smem (bytes) ----
#define SO_SCN   0                        // 1024 f32 cnorm
#define SO_MK    4096                     // 128 i32
#define SO_MB    4608                     // 128 f32
#define SO_A     5120                     // 32 KB A fp16 fragments
#define SO_B0    (SO_A + 32768)           // 37888
#define SO_B1    (SO_B0 + 32768)          // 70656; also raw-input staging
#define SMEM_TOTAL (SO_B1 + 32768)        // 103424 B -> 2 CTAs/SM

#define STAGE_STRIDE 128                  // floats per staged dim row (fits B1)

// ---------------------------------------------------------------------------
__device__ __forceinline__ uint32_t smem_u32(const void* p) {
    uint32_t a;
    asm("{ .reg .u64 t; cvta.to.shared.u64 t, %1; cvt.u32.u64 %0, t; }"
        : "=r"(a) : "l"(p));
    return a;
}
__device__ __forceinline__ void cp_async16(uint32_t dst, const void* src) {
    asm volatile("cp.async.cg.shared.global [%0], [%1], 16;"
                 :: "r"(dst), "l"(src) : "memory");
}
#define CP_COMMIT() asm volatile("cp.async.commit_group;" ::: "memory")

__device__ __forceinline__ void lds128(uint32_t* r, uint32_t a) {
    asm volatile("ld.shared.v4.b32 {%0,%1,%2,%3}, [%4];"
                 : "=r"(r[0]), "=r"(r[1]), "=r"(r[2]), "=r"(r[3]) : "r"(a));
}
__device__ __forceinline__ void lds64(uint32_t* r, uint32_t a) {
    asm volatile("ld.shared.v2.b32 {%0,%1}, [%2];"
                 : "=r"(r[0]), "=r"(r[1]) : "r"(a));
}
__device__ __forceinline__ void sts128u(uint32_t a, uint32_t x, uint32_t y,
                                        uint32_t z, uint32_t w) {
    asm volatile("st.shared.v4.b32 [%0], {%1,%2,%3,%4};"
                 :: "r"(a), "r"(x), "r"(y), "r"(z), "r"(w) : "memory");
}
__device__ __forceinline__ void mma_f16(float* c, const uint32_t* a, const uint32_t* b) {
    asm volatile(
        "mma.sync.aligned.m16n8k16.row.col.f32.f16.f16.f32 "
        "{%0,%1,%2,%3}, {%4,%5,%6,%7}, {%8,%9}, {%0,%1,%2,%3};"
        : "+f"(c[0]), "+f"(c[1]), "+f"(c[2]), "+f"(c[3])
        : "r"(a[0]), "r"(a[1]), "r"(a[2]), "r"(a[3]), "r"(b[0]), "r"(b[1]));
}
__device__ __forceinline__ uint32_t packh2(__half lo, __half hi) {
    __half2 h = __halves2half2(lo, hi);
    return *reinterpret_cast<uint32_t*>(&h);
}
// value at concatenated column c (0-63: h1(dim c), 64-127: h2(dim c-64))
__device__ __forceinline__ __half split_h(float x, int c) {
    __half h1 = __float2half_rn(x);
    if (c < 64) return h1;
    return __float2half_rn(x - __half2float(h1));
}

// ---------------------------------------------------------------------------
// Prep: codebook -> g_Cf fp16 fragments + cnorm. 32 blocks (chunk, quarter).
// ---------------------------------------------------------------------------
__global__ __launch_bounds__(256) void prep_codebook(const float* __restrict__ cb) {
    __shared__ float sc[32][65];
    const int t = threadIdx.x;
    const int c = blockIdx.x >> 2;
    const int q = blockIdx.x & 3;
    const int base = c * 128 + q * 32;
#pragma unroll
    for (int it = 0; it < 8; it++) {
        int idx = it * 256 + t;
        int n = idx >> 6, d = idx & 63;
        sc[n][d] = cb[(size_t)(base + n) * DDIM + d];
    }
    __syncthreads();
    if (t < 32) {
        float s = 0.f;
#pragma unroll
        for (int d = 0; d < DDIM; d++) s = fmaf(sc[t][d], sc[t][d], s);
        g_cnorm[base + t] = s;
    }
#pragma unroll
    for (int it = 0; it < 4; it++) {
        int fi = it * 256 + t;
        int ks = fi >> 7, ntl = (fi >> 5) & 3, lane = fi & 31;
        int g = lane >> 2, tg = lane & 3;
        int nl = ntl * 8 + g;
        int c0 = ks * 16 + tg * 2;
        int d0 = c0 & 63;
        uint32_t b0 = packh2(split_h(sc[nl][d0],     c0),
                             split_h(sc[nl][d0 + 1], c0 + 1));
        uint32_t b1 = packh2(split_h(sc[nl][d0 + 8], c0 + 8),
                             split_h(sc[nl][d0 + 9], c0 + 9));
        g_Cf[(((size_t)c * 8 + ks) * 16 + (q * 4 + ntl)) * 32 + lane] =
            make_uint2(b0, b1);
    }
}

// ---------------------------------------------------------------------------
// Main: 128 points x 1024 codes per CTA (512 CTAs), 8 warps, 32x64 warp tile.
// ---------------------------------------------------------------------------
__global__ __launch_bounds__(NTHREADS, 2)
void vq_mma_kernel(const float* __restrict__ input,
                   const float* __restrict__ codebook,
                   float* __restrict__ out_idx,
                   float* __restrict__ out_embed) {
    extern __shared__ char smem[];
    const uint32_t sb = smem_u32(smem);
    const int tid  = threadIdx.x;
    const int wid  = tid >> 5;
    const int lane = tid & 31;
    const int g    = lane >> 2;
    const int tg   = lane & 3;
    const int wm   = wid & 3;      // rows [wm*32, wm*32+32)
    const int wn   = wid >> 2;     // cols [wn*64, wn*64+64)
    const int mtb  = wm * 2;       // base 16-row mma tile index

    const int bm  = blockIdx.x;
    const int b   = bm >> 3;
    const int hw0 = (bm & 7) * 128;

    // ---- G0: raw input tile (64 dims x 128 pts) -> staging (B1), + cnorm ----
    {
        const float* src = input + (size_t)b * (DDIM * HWD) + hw0;
#pragma unroll
        for (int it = 0; it < 8; it++) {
            int idx = it * NTHREADS + tid;          // 2048 x 16B
            int row = idx >> 5, seg = idx & 31;
            cp_async16(sb + SO_B1 + (uint32_t)(row * (STAGE_STRIDE * 4) + seg * 16),
                       src + (size_t)row * HWD + seg * 4);
        }
        const float4* cn4 = reinterpret_cast<const float4*>(g_cnorm);
        cp_async16(sb + SO_SCN + tid * 16, cn4 + tid);
        CP_COMMIT();                            // G0
    }
    // ---- G1: B chunk 0 -> B0 (32 KB) ----
    {
        const float4* Bsrc = reinterpret_cast<const float4*>(g_Cf);
#pragma unroll
        for (int it = 0; it < 8; it++) {
            int idx = it * NTHREADS + tid;
            cp_async16(sb + SO_B0 + idx * 16, Bsrc + idx);
        }
        CP_COMMIT();                            // G1
    }

    // ---- convert raw -> A fp16 fragments: 2048 entries [ks][mt][lane] ----
    asm volatile("cp.async.wait_group 1;" ::: "memory");   // G0 done
    __syncthreads();
    {
        const float* stage = reinterpret_cast<const float*>(smem + SO_B1);
#pragma unroll
        for (int it = 0; it < 8; it++) {
            int fi = it * NTHREADS + tid;
            int ks = fi >> 8, mt = (fi >> 5) & 7, ln = fi & 31;
            int gg = ln >> 2, t4 = ln & 3;
            int r0 = mt * 16 + gg, r1 = r0 + 8;
            int c0 = ks * 16 + t4 * 2;
            int d0 = c0 & 63;
            uint32_t a0 = packh2(split_h(stage[(d0)     * STAGE_STRIDE + r0], c0),
                                 split_h(stage[(d0 + 1) * STAGE_STRIDE + r0], c0 + 1));
            uint32_t a1 = packh2(split_h(stage[(d0)     * STAGE_STRIDE + r1], c0),
                                 split_h(stage[(d0 + 1) * STAGE_STRIDE + r1], c0 + 1));
            uint32_t a2 = packh2(split_h(stage[(d0 + 8) * STAGE_STRIDE + r0], c0 + 8),
                                 split_h(stage[(d0 + 9) * STAGE_STRIDE + r0], c0 + 9));
            uint32_t a3 = packh2(split_h(stage[(d0 + 8) * STAGE_STRIDE + r1], c0 + 8),
                                 split_h(stage[(d0 + 9) * STAGE_STRIDE + r1], c0 + 9));
            sts128u(sb + SO_A + fi * 16, a0, a1, a2, a3);
        }
    }
    __syncthreads();   // A ready; staging (B1) dead

    // ---- h1 A fragments for mtile mtb -> registers (16 regs) ----
    uint32_t At1[4][4];
#pragma unroll
    for (int kk = 0; kk < 4; kk++)
        lds128(At1[kk], sb + SO_A + (uint32_t)(((kk * 8 + mtb) * 32 + lane) * 16));

    // ---- G2: B chunk 1 -> B1 ----
    {
        const float4* Bsrc = reinterpret_cast<const float4*>(g_Cf) + 2048;
#pragma unroll
        for (int it = 0; it < 8; it++) {
            int idx = it * NTHREADS + tid;
            cp_async16(sb + SO_B1 + idx * 16, Bsrc + idx);
        }
        CP_COMMIT();                            // G2
    }

    const float* scn = reinterpret_cast<const float*>(smem + SO_SCN);
    float best[4];
    int   bestk[4];
#pragma unroll
    for (int i = 0; i < 4; i++) { best[i] = __int_as_float(0x7f7fffff); bestk[i] = 0; }

    const uint32_t bOffW = (uint32_t)((wn * 8 * 32 + lane) * 8);
    const uint32_t aL    = sb + SO_A + (uint32_t)(lane * 16);

    for (int ch = 0; ch < NCHUNKS; ch++) {
        if (ch < NCHUNKS - 1) asm volatile("cp.async.wait_group 1;" ::: "memory");
        else                  asm volatile("cp.async.wait_group 0;" ::: "memory");
        __syncthreads();

        const uint32_t bBase = sb + ((ch & 1) ? SO_B1 : SO_B0) + bOffW;

        float acc[2][8][4];
#pragma unroll
        for (int mt = 0; mt < 2; mt++)
#pragma unroll
            for (int nt = 0; nt < 8; nt++)
#pragma unroll
                for (int j = 0; j < 4; j++) acc[mt][nt][j] = 0.f;

#pragma unroll
        for (int k = 0; k < 8; k++) {
            uint32_t bf[8][2];
#pragma unroll
            for (int nt = 0; nt < 8; nt++)
                lds64(bf[nt], bBase + (uint32_t)(((k * 16 + nt) * 32) * 8));

            if (k < 4) {
                // B-h1 kstep k: feeds (A-h1, A-h2) x both mtiles
                uint32_t aA[4], aB[4], aC[4];
                lds128(aA, aL + (uint32_t)((((k + 4) * 8 + mtb) * 32) * 16));     // mt0 h2
                lds128(aB, aL + (uint32_t)(((k * 8 + mtb + 1) * 32) * 16));       // mt1 h1
                lds128(aC, aL + (uint32_t)((((k + 4) * 8 + mtb + 1) * 32) * 16)); // mt1 h2
#pragma unroll
                for (int nt = 0; nt < 8; nt++) mma_f16(acc[0][nt], At1[k], bf[nt]);
#pragma unroll
                for (int nt = 0; nt < 8; nt++) mma_f16(acc[1][nt], aB, bf[nt]);
#pragma unroll
                for (int nt = 0; nt < 8; nt++) mma_f16(acc[0][nt], aA, bf[nt]);
#pragma unroll
                for (int nt = 0; nt < 8; nt++) mma_f16(acc[1][nt], aC, bf[nt]);
            } else {
                // B-h2 kstep (k-4): feeds A-h1 x both mtiles
                const int kk = k - 4;
                uint32_t aB[4];
                lds128(aB, aL + (uint32_t)(((kk * 8 + mtb + 1) * 32) * 16));      // mt1 h1
#pragma unroll
                for (int nt = 0; nt < 8; nt++) mma_f16(acc[0][nt], At1[kk], bf[nt]);
#pragma unroll
                for (int nt = 0; nt < 8; nt++) mma_f16(acc[1][nt], aB, bf[nt]);
            }
        }

        // ---- argmin fold ----
        {
            const int cb0 = ch * 128 + wn * 64;
#pragma unroll
            for (int mt = 0; mt < 2; mt++)
#pragma unroll
                for (int nt = 0; nt < 8; nt++) {
                    int col = cb0 + nt * 8 + tg * 2;
                    float n0 = scn[col], n1 = scn[col + 1];
#pragma unroll
                    for (int hi = 0; hi < 2; hi++) {
                        float d0 = fmaf(-2.f, acc[mt][nt][hi * 2 + 0], n0);
                        float d1 = fmaf(-2.f, acc[mt][nt][hi * 2 + 1], n1);
                        int bi = mt * 2 + hi;
                        if (d0 < best[bi]) { best[bi] = d0; bestk[bi] = col; }
                        if (d1 < best[bi]) { best[bi] = d1; bestk[bi] = col + 1; }
                    }
                }
        }

        __syncthreads();   // buffer (ch&1) fully consumed before refill
        if (ch + 2 < NCHUNKS) {
            const float4* Bsrc = reinterpret_cast<const float4*>(g_Cf)
                                 + (size_t)(ch + 2) * 2048;
            const uint32_t bdst = sb + ((ch & 1) ? SO_B1 : SO_B0);
#pragma unroll
            for (int it = 0; it < 8; it++) {
                int idx = it * NTHREADS + tid;
                cp_async16(bdst + idx * 16, Bsrc + idx);
            }
            CP_COMMIT();
        }
    }

    // ---- reduce 4 lanes (tg) sharing each row ----
#pragma unroll
    for (int i = 0; i < 4; i++) {
#pragma unroll
        for (int off = 1; off <= 2; off <<= 1) {
            float ob = __shfl_xor_sync(0xffffffffu, best[i], off);
            int   ok = __shfl_xor_sync(0xffffffffu, bestk[i], off);
            if (ob < best[i] || (ob == best[i] && ok < bestk[i])) {
                best[i] = ob; bestk[i] = ok;
            }
        }
    }

    // ---- merge the two warps (wn) sharing each row ----
    float* mb = reinterpret_cast<float*>(smem + SO_MB);
    int*   mk = reinterpret_cast<int*>(smem + SO_MK);
    if (wn == 0 && tg == 0) {
#pragma unroll
        for (int i = 0; i < 4; i++) {
            int r = (mtb + (i >> 1)) * 16 + g + 8 * (i & 1);
            mb[r] = best[i]; mk[r] = bestk[i];
        }
    }
    __syncthreads();
    if (wn == 1 && tg == 0) {
#pragma unroll
        for (int i = 0; i < 4; i++) {
            int r = (mtb + (i >> 1)) * 16 + g + 8 * (i & 1);
            float ob = mb[r]; int ok = mk[r];
            if (best[i] < ob || (best[i] == ob && bestk[i] < ok)) {
                mb[r] = best[i]; mk[r] = bestk[i];
            }
        }
    }
    __syncthreads();

    if (out_idx && tid < 128) out_idx[bm * 128 + tid] = (float)mk[tid];

    // ---- embed gather: 256 threads, 32 channels each ----
    if (out_embed) {
        int p  = bm * 128 + (tid & 127);
        int k  = mk[tid & 127];
        int bb = p >> 10, hw = p & 1023;
        int d0 = (tid >> 7) * 32;
        const float* crow = codebook + (size_t)k * DDIM + d0;
        float* op = out_embed + (size_t)bb * (DDIM * HWD) + (size_t)d0 * HWD + hw;
#pragma unroll
        for (int d = 0; d < 32; d++) op[(size_t)d * HWD] = __ldg(crow + d);
    }
}

// ---------------------------------------------------------------------------
extern "C" void kernel_launch(void* const* d_in, const int* in_sizes, int n_in,
                              void* d_out, int out_size) {
    const float* input    = (const float*)d_in[0];
    const float* codebook = (const float*)d_in[1];
    if (n_in >= 2 && in_sizes[0] == KCODES * DDIM && in_sizes[1] == NPTS * DDIM) {
        codebook = (const float*)d_in[0];
        input    = (const float*)d_in[1];
    }

    float* out = (float*)d_out;
    float* out_idx   = nullptr;
    float* out_embed = nullptr;
    if (out_size >= NPTS + NPTS * DDIM) {
        out_idx   = out;
        out_embed = out + NPTS;
    } else if (out_size == NPTS * DDIM) {
        out_embed = out;
    } else {
        out_idx = out;
    }

    cudaFuncSetAttribute(vq_mma_kernel,
                         cudaFuncAttributeMaxDynamicSharedMemorySize, SMEM_TOTAL);

    prep_codebook<<<32, 256>>>(codebook);
    vq_mma_kernel<<<NPTS / 128, NTHREADS, SMEM_TOTAL>>>(input, codebook,
                                                        out_idx, out_embed);
}

// round 8
// speedup vs baseline: 3.2931x; 1.0281x over previous
#include <cuda_runtime.h>
#include <cuda_fp16.h>
#include <cstdint>

// VQ layer via legacy mma.sync fp16 m16n8k16 (base sm_100 target).
//
// input (B=64, D=64, H=32, W=32) f32 ; codebook (K=1024, D=64) f32
// out f32: [idxes (65536)] [embed (4194304, layout (B,D,H,W))]
//
// d2 = ||c||^2 - 2 x.c ; fp16 2-split (h1 has tf32-grade 11-bit significand):
// dot = h1x.h1c + h1x.h2c + h2x.h1c, f32 accumulate, error ~2^-22.
// R8: 64-code chunks (16), triple-buffered B, ALL A fragments (h1+h2, 2
// mtiles) register-resident -> zero A smem traffic in mainloop; one
// __syncthreads per chunk.

#define NPTS    65536
#define DDIM    64
#define KCODES  1024
#define HWD     1024
#define NCHUNKS 16       // 16 x 64 codes
#define NTHREADS 256

// B fragments fp16: [chunk 0..15][ks 0..7][nt 0..7][lane 0..31] uint2
//   ks 0-3 = h1 cols (dims 16k..), ks 4-7 = h2 cols.
__device__ uint2 g_Cf[NCHUNKS * 8 * 8 * 32];    // 256 KB (L2-resident)
__device__ float g_cnorm[KCODES];

// ---- dynamic smem (bytes) ----
#define SO_SCN   0                        // 1024 f32 cnorm
#define SO_MK    4096                     // 128 i32
#define SO_MB    4608                     // 128 f32
#define SO_A     5120                     // 32 KB A fp16 fragments (transit)
#define SO_B     37888                    // 3 x 16384 B ring; also raw staging
#define SMEM_TOTAL (SO_B + 3 * 16384)     // 87040 B -> 2 CTAs/SM

#define STAGE_STRIDE 128                  // floats per staged dim row

// ---------------------------------------------------------------------------
__device__ __forceinline__ uint32_t smem_u32(const void* p) {
    uint32_t a;
    asm("{ .reg .u64 t; cvta.to.shared.u64 t, %1; cvt.u32.u64 %0, t; }"
        : "=r"(a) : "l"(p));
    return a;
}
__device__ __forceinline__ void cp_async16(uint32_t dst, const void* src) {
    asm volatile("cp.async.cg.shared.global [%0], [%1], 16;"
                 :: "r"(dst), "l"(src) : "memory");
}
#define CP_COMMIT() asm volatile("cp.async.commit_group;" ::: "memory")

__device__ __forceinline__ void lds128(uint32_t* r, uint32_t a) {
    asm volatile("ld.shared.v4.b32 {%0,%1,%2,%3}, [%4];"
                 : "=r"(r[0]), "=r"(r[1]), "=r"(r[2]), "=r"(r[3]) : "r"(a));
}
__device__ __forceinline__ void lds64(uint32_t* r, uint32_t a) {
    asm volatile("ld.shared.v2.b32 {%0,%1}, [%2];"
                 : "=r"(r[0]), "=r"(r[1]) : "r"(a));
}
__device__ __forceinline__ void sts128u(uint32_t a, uint32_t x, uint32_t y,
                                        uint32_t z, uint32_t w) {
    asm volatile("st.shared.v4.b32 [%0], {%1,%2,%3,%4};"
                 :: "r"(a), "r"(x), "r"(y), "r"(z), "r"(w) : "memory");
}
__device__ __forceinline__ void mma_f16(float* c, const uint32_t* a, const uint32_t* b) {
    asm volatile(
        "mma.sync.aligned.m16n8k16.row.col.f32.f16.f16.f32 "
        "{%0,%1,%2,%3}, {%4,%5,%6,%7}, {%8,%9}, {%0,%1,%2,%3};"
        : "+f"(c[0]), "+f"(c[1]), "+f"(c[2]), "+f"(c[3])
        : "r"(a[0]), "r"(a[1]), "r"(a[2]), "r"(a[3]), "r"(b[0]), "r"(b[1]));
}
__device__ __forceinline__ uint32_t packh2(__half lo, __half hi) {
    __half2 h = __halves2half2(lo, hi);
    return *reinterpret_cast<uint32_t*>(&h);
}
// value at concatenated column c (0-63: h1(dim c), 64-127: h2(dim c-64))
__device__ __forceinline__ __half split_h(float x, int c) {
    __half h1 = __float2half_rn(x);
    if (c < 64) return h1;
    return __float2half_rn(x - __half2float(h1));
}

// ---------------------------------------------------------------------------
// Prep: codebook -> g_Cf fp16 fragments + cnorm. 32 blocks of 32 codes.
// ---------------------------------------------------------------------------
__global__ __launch_bounds__(256) void prep_codebook(const float* __restrict__ cb) {
    __shared__ float sc[32][65];
    const int t = threadIdx.x;
    const int base = blockIdx.x * 32;       // first code
    const int c  = blockIdx.x >> 1;         // 64-code chunk
    const int qh = blockIdx.x & 1;          // nt half within chunk
#pragma unroll
    for (int it = 0; it < 8; it++) {
        int idx = it * 256 + t;
        int n = idx >> 6, d = idx & 63;
        sc[n][d] = cb[(size_t)(base + n) * DDIM + d];
    }
    __syncthreads();
    if (t < 32) {
        float s = 0.f;
#pragma unroll
        for (int d = 0; d < DDIM; d++) s = fmaf(sc[t][d], sc[t][d], s);
        g_cnorm[base + t] = s;
    }
    // 1024 fragment entries per block: [ks 0..7][ntl 0..3][lane]
#pragma unroll
    for (int it = 0; it < 4; it++) {
        int fi = it * 256 + t;
        int ks = fi >> 7, ntl = (fi >> 5) & 3, lane = fi & 31;
        int g = lane >> 2, tg = lane & 3;
        int nl = ntl * 8 + g;                // local code 0..31
        int c0 = ks * 16 + tg * 2;           // concat col
        int d0 = c0 & 63;
        uint32_t b0 = packh2(split_h(sc[nl][d0],     c0),
                             split_h(sc[nl][d0 + 1], c0 + 1));
        uint32_t b1 = packh2(split_h(sc[nl][d0 + 8], c0 + 8),
                             split_h(sc[nl][d0 + 9], c0 + 9));
        g_Cf[(((size_t)c * 8 + ks) * 8 + (qh * 4 + ntl)) * 32 + lane] =
            make_uint2(b0, b1);
    }
}

// ---------------------------------------------------------------------------
// Main: 128 points x 1024 codes per CTA (512 CTAs), 8 warps, 32x32 sub-chunk.
// ---------------------------------------------------------------------------
__global__ __launch_bounds__(NTHREADS, 2)
void vq_mma_kernel(const float* __restrict__ input,
                   const float* __restrict__ codebook,
                   float* __restrict__ out_idx,
                   float* __restrict__ out_embed) {
    extern __shared__ char smem[];
    const uint32_t sb = smem_u32(smem);
    const int tid  = threadIdx.x;
    const int wid  = tid >> 5;
    const int lane = tid & 31;
    const int g    = lane >> 2;
    const int tg   = lane & 3;
    const int wm   = wid & 3;      // rows [wm*32, wm*32+32)
    const int wn   = wid >> 2;     // cols [wn*32, wn*32+32) of 64-code chunk
    const int mtb  = wm * 2;       // base 16-row mma tile index

    const int bm  = blockIdx.x;
    const int b   = bm >> 3;
    const int hw0 = (bm & 7) * 128;

    // ---- G0: raw input tile (64 dims x 128 pts) -> B ring area, + cnorm ----
    {
        const float* src = input + (size_t)b * (DDIM * HWD) + hw0;
#pragma unroll
        for (int it = 0; it < 8; it++) {
            int idx = it * NTHREADS + tid;          // 2048 x 16B
            int row = idx >> 5, seg = idx & 31;
            cp_async16(sb + SO_B + (uint32_t)(row * (STAGE_STRIDE * 4) + seg * 16),
                       src + (size_t)row * HWD + seg * 4);
        }
        const float4* cn4 = reinterpret_cast<const float4*>(g_cnorm);
        cp_async16(sb + SO_SCN + tid * 16, cn4 + tid);
        CP_COMMIT();                            // G0
    }
    // ---- G1: chunk 0 -> ring buf 2 (beyond staging area) ----
    {
        const float4* Bsrc = reinterpret_cast<const float4*>(g_Cf);
#pragma unroll
        for (int it = 0; it < 4; it++) {
            int idx = it * NTHREADS + tid;          // 1024 x 16B
            cp_async16(sb + SO_B + 2 * 16384 + idx * 16, Bsrc + idx);
        }
        CP_COMMIT();                            // G1
    }

    // ---- convert raw -> A fp16 fragments in SO_A: [ks 0..7][mt 0..7][lane] ----
    asm volatile("cp.async.wait_group 1;" ::: "memory");   // G0 done
    __syncthreads();
    {
        const float* stage = reinterpret_cast<const float*>(smem + SO_B);
#pragma unroll
        for (int it = 0; it < 8; it++) {
            int fi = it * NTHREADS + tid;          // 2048 entries
            int ks = fi >> 8, mt = (fi >> 5) & 7, ln = fi & 31;
            int gg = ln >> 2, t4 = ln & 3;
            int r0 = mt * 16 + gg, r1 = r0 + 8;
            int c0 = ks * 16 + t4 * 2;
            int d0 = c0 & 63;
            uint32_t a0 = packh2(split_h(stage[(d0)     * STAGE_STRIDE + r0], c0),
                                 split_h(stage[(d0 + 1) * STAGE_STRIDE + r0], c0 + 1));
            uint32_t a1 = packh2(split_h(stage[(d0)     * STAGE_STRIDE + r1], c0),
                                 split_h(stage[(d0 + 1) * STAGE_STRIDE + r1], c0 + 1));
            uint32_t a2 = packh2(split_h(stage[(d0 + 8) * STAGE_STRIDE + r0], c0 + 8),
                                 split_h(stage[(d0 + 9) * STAGE_STRIDE + r0], c0 + 9));
            uint32_t a3 = packh2(split_h(stage[(d0 + 8) * STAGE_STRIDE + r1], c0 + 8),
                                 split_h(stage[(d0 + 9) * STAGE_STRIDE + r1], c0 + 9));
            sts128u(sb + SO_A + fi * 16, a0, a1, a2, a3);
        }
    }
    __syncthreads();   // A fragments ready; staging area (ring bufs 0,1) dead

    // ---- ALL A fragments for this warp's 2 mtiles -> 64 registers ----
    uint32_t Ah1[4][2][4], Ah2[4][2][4];
#pragma unroll
    for (int k = 0; k < 4; k++)
#pragma unroll
        for (int mt = 0; mt < 2; mt++) {
            lds128(Ah1[k][mt],
                   sb + SO_A + (uint32_t)(((k * 8 + mtb + mt) * 32 + lane) * 16));
            lds128(Ah2[k][mt],
                   sb + SO_A + (uint32_t)((((k + 4) * 8 + mtb + mt) * 32 + lane) * 16));
        }

    // ---- G2: chunk 1 -> ring buf 0 ; G3: chunk 2 -> ring buf 1 ----
    {
        const float4* Bsrc = reinterpret_cast<const float4*>(g_Cf);
#pragma unroll
        for (int it = 0; it < 4; it++) {
            int idx = it * NTHREADS + tid;
            cp_async16(sb + SO_B + idx * 16, Bsrc + 1024 + idx);
        }
        CP_COMMIT();                            // G2
#pragma unroll
        for (int it = 0; it < 4; it++) {
            int idx = it * NTHREADS + tid;
            cp_async16(sb + SO_B + 16384 + idx * 16, Bsrc + 2048 + idx);
        }
        CP_COMMIT();                            // G3
    }

    const float* scn = reinterpret_cast<const float*>(smem + SO_SCN);
    float best[4];
    int   bestk[4];
#pragma unroll
    for (int i = 0; i < 4; i++) { best[i] = __int_as_float(0x7f7fffff); bestk[i] = 0; }

    const uint32_t bOffW = (uint32_t)((wn * 4 * 32 + lane) * 8);

    // buf(ch) = (ch + 2) % 3
    for (int ch = 0; ch < NCHUNKS; ch++) {
        if (ch < NCHUNKS - 1) asm volatile("cp.async.wait_group 1;" ::: "memory");
        else                  asm volatile("cp.async.wait_group 0;" ::: "memory");
        __syncthreads();   // chunk ch data visible; all warps done with ch-1

        // refill: chunk ch+2 -> buf (ch+1)%3 (consumed at chunk ch-1)
        if (ch >= 1 && ch + 2 < NCHUNKS) {
            const float4* Bsrc = reinterpret_cast<const float4*>(g_Cf)
                                 + (size_t)(ch + 2) * 1024;
            const uint32_t bdst = sb + SO_B + (uint32_t)(((ch + 1) % 3) * 16384);
#pragma unroll
            for (int it = 0; it < 4; it++) {
                int idx = it * NTHREADS + tid;
                cp_async16(bdst + idx * 16, Bsrc + idx);
            }
            CP_COMMIT();
        }

        const uint32_t bBase = sb + SO_B + (uint32_t)((((ch + 2) % 3)) * 16384) + bOffW;

        float acc[2][4][4];
#pragma unroll
        for (int mt = 0; mt < 2; mt++)
#pragma unroll
            for (int nt = 0; nt < 4; nt++)
#pragma unroll
                for (int j = 0; j < 4; j++) acc[mt][nt][j] = 0.f;

        // ksteps 0-3: B-h1 feeds (A-h1, A-h2) x both mtiles (16 MMA each)
#pragma unroll
        for (int k = 0; k < 4; k++) {
            uint32_t bf[4][2];
#pragma unroll
            for (int nt = 0; nt < 4; nt++)
                lds64(bf[nt], bBase + (uint32_t)((k * 8 + nt) * 256));
#pragma unroll
            for (int nt = 0; nt < 4; nt++) mma_f16(acc[0][nt], Ah1[k][0], bf[nt]);
#pragma unroll
            for (int nt = 0; nt < 4; nt++) mma_f16(acc[1][nt], Ah1[k][1], bf[nt]);
#pragma unroll
            for (int nt = 0; nt < 4; nt++) mma_f16(acc[0][nt], Ah2[k][0], bf[nt]);
#pragma unroll
            for (int nt = 0; nt < 4; nt++) mma_f16(acc[1][nt], Ah2[k][1], bf[nt]);
        }
        // ksteps 4-7: B-h2 feeds A-h1 x both mtiles (8 MMA each)
#pragma unroll
        for (int k = 4; k < 8; k++) {
            uint32_t bf[4][2];
#pragma unroll
            for (int nt = 0; nt < 4; nt++)
                lds64(bf[nt], bBase + (uint32_t)((k * 8 + nt) * 256));
#pragma unroll
            for (int nt = 0; nt < 4; nt++) mma_f16(acc[0][nt], Ah1[k - 4][0], bf[nt]);
#pragma unroll
            for (int nt = 0; nt < 4; nt++) mma_f16(acc[1][nt], Ah1[k - 4][1], bf[nt]);
        }

        // ---- argmin fold (32 elements/lane) ----
        {
            const int cb0 = ch * 64 + wn * 32;
#pragma unroll
            for (int mt = 0; mt < 2; mt++)
#pragma unroll
                for (int nt = 0; nt < 4; nt++) {
                    int col = cb0 + nt * 8 + tg * 2;
                    float n0 = scn[col], n1 = scn[col + 1];
#pragma unroll
                    for (int hi = 0; hi < 2; hi++) {
                        float d0 = fmaf(-2.f, acc[mt][nt][hi * 2 + 0], n0);
                        float d1 = fmaf(-2.f, acc[mt][nt][hi * 2 + 1], n1);
                        int bi = mt * 2 + hi;
                        if (d0 < best[bi]) { best[bi] = d0; bestk[bi] = col; }
                        if (d1 < best[bi]) { best[bi] = d1; bestk[bi] = col + 1; }
                    }
                }
        }
        // NOTE: no trailing barrier — next iteration's top barrier protects
        // the refill (buffer written at top of ch+1 was consumed at ch-1).
    }

    // ---- reduce 4 lanes (tg) sharing each row ----
#pragma unroll
    for (int i = 0; i < 4; i++) {
#pragma unroll
        for (int off = 1; off <= 2; off <<= 1) {
            float ob = __shfl_xor_sync(0xffffffffu, best[i], off);
            int   ok = __shfl_xor_sync(0xffffffffu, bestk[i], off);
            if (ob < best[i] || (ob == best[i] && ok < bestk[i])) {
                best[i] = ob; bestk[i] = ok;
            }
        }
    }

    // ---- merge the two warps (wn) sharing each row ----
    float* mb = reinterpret_cast<float*>(smem + SO_MB);
    int*   mk = reinterpret_cast<int*>(smem + SO_MK);
    if (wn == 0 && tg == 0) {
#pragma unroll
        for (int i = 0; i < 4; i++) {
            int r = (mtb + (i >> 1)) * 16 + g + 8 * (i & 1);
            mb[r] = best[i]; mk[r] = bestk[i];
        }
    }
    __syncthreads();
    if (wn == 1 && tg == 0) {
#pragma unroll
        for (int i = 0; i < 4; i++) {
            int r = (mtb + (i >> 1)) * 16 + g + 8 * (i & 1);
            float ob = mb[r]; int ok = mk[r];
            if (best[i] < ob || (best[i] == ob && bestk[i] < ok)) {
                mb[r] = best[i]; mk[r] = bestk[i];
            }
        }
    }
    __syncthreads();

    if (out_idx && tid < 128) out_idx[bm * 128 + tid] = (float)mk[tid];

    // ---- embed gather: 256 threads, 32 channels each ----
    if (out_embed) {
        int p  = bm * 128 + (tid & 127);
        int k  = mk[tid & 127];
        int bb = p >> 10, hw = p & 1023;
        int d0 = (tid >> 7) * 32;
        const float* crow = codebook + (size_t)k * DDIM + d0;
        float* op = out_embed + (size_t)bb * (DDIM * HWD) + (size_t)d0 * HWD + hw;
#pragma unroll
        for (int d = 0; d < 32; d++) op[(size_t)d * HWD] = __ldg(crow + d);
    }
}

// ---------------------------------------------------------------------------
extern "C" void kernel_launch(void* const* d_in, const int* in_sizes, int n_in,
                              void* d_out, int out_size) {
    const float* input    = (const float*)d_in[0];
    const float* codebook = (const float*)d_in[1];
    if (n_in >= 2 && in_sizes[0] == KCODES * DDIM && in_sizes[1] == NPTS * DDIM) {
        codebook = (const float*)d_in[0];
        input    = (const float*)d_in[1];
    }

    float* out = (float*)d_out;
    float* out_idx   = nullptr;
    float* out_embed = nullptr;
    if (out_size >= NPTS + NPTS * DDIM) {
        out_idx   = out;
        out_embed = out + NPTS;
    } else if (out_size == NPTS * DDIM) {
        out_embed = out;
    } else {
        out_idx = out;
    }

    cudaFuncSetAttribute(vq_mma_kernel,
                         cudaFuncAttributeMaxDynamicSharedMemorySize, SMEM_TOTAL);

    prep_codebook<<<32, 256>>>(codebook);
    vq_mma_kernel<<<NPTS / 128, NTHREADS, SMEM_TOTAL>>>(input, codebook,
                                                        out_idx, out_embed);
}